// round 13
// baseline (speedup 1.0000x reference)
#include <cuda_runtime.h>
#include <cuda_fp16.h>
#include <stdint.h>
#include <math.h>

// Problem constants
#define TTOK 4096
#define HDIM 1024
#define IDIM 2048
#define NE   8
#define NPAIR (TTOK * 2)

// GEMM config: 128x128 CTA tile, 4 warps (2M x 2N of 64x64 warp tiles), KC=64
#define KC 64
#define A_PITCH 144              // bytes per smem row (64 fp16 + pad; ldmatrix conflict-free)
#define SM_A 0
#define SM_B (128 * A_PITCH)                 // 18432
#define SM_STAGE (2 * 128 * A_PITCH)         // 36864
#define SMEM_GEMM (2 * SM_STAGE)             // 73728 -> 2 CTAs/SM
#define GTHR 128                              // GEMM threads per CTA

// prep-kernel job ranges
#define PREP_R 512                            // router: 8 tokens/block
#define PREP_G 32768                          // gup transpose: 128 x 32 x 8
#define PREP_D 16384                          // dwn transpose: 32 x 64 x 8
#define PREP_S 2048                           // shared cvt: (I*H)/1024
#define PREP_TOTAL (PREP_R + PREP_G + PREP_D + PREP_S)

// ---------------- scratch (static __device__ — no allocation) ----------------
__device__ __half g_x[(size_t)TTOK * HDIM];             // x fp16 (written by router)
__device__ __half g_act[(size_t)NPAIR * IDIM];          // routed swiglu act fp16
__device__ __half g_acts[(size_t)TTOK * IDIM];          // shared swiglu act fp16
__device__ float g_partial[2][(size_t)TTOK * HDIM];     // per-slot routed outputs
__device__ int   g_row_tok[NPAIR];
__device__ float g_row_sc[NPAIR];
__device__ int   g_row_slot[NPAIR];
__device__ int   g_tope[NPAIR];
__device__ float g_tops[NPAIR];
__device__ int   g_cnt[NE];
__device__ int   g_off[NE];

// fp16 weights, [n][k] col-major-for-mma layouts
__device__ __half g_wgu[(size_t)NE * 2 * IDIM * HDIM];   // interleaved gate/up rows
__device__ __half g_wdn[(size_t)NE * HDIM * IDIM];       // [H][I]
__device__ __half g_wsg[(size_t)2 * IDIM * HDIM];        // shared gate/up interleaved
__device__ __half g_wsd[(size_t)HDIM * IDIM];            // [H][I]

// ---------------- small helpers ----------------
__device__ __forceinline__ uint32_t smem_u32(const void* p) {
    uint32_t a;
    asm("{ .reg .u64 t; cvta.to.shared.u64 t, %1; cvt.u32.u64 %0, t; }" : "=r"(a) : "l"(p));
    return a;
}
__device__ __forceinline__ void cpa16(uint32_t saddr, const void* g) {
    asm volatile("cp.async.ca.shared.global [%0], [%1], 16;" :: "r"(saddr), "l"(g));
}
__device__ __forceinline__ void cpa_commit() {
    asm volatile("cp.async.commit_group;" ::: "memory");
}
__device__ __forceinline__ void cpa_wait0() {
    asm volatile("cp.async.wait_group 0;" ::: "memory");
}
__device__ __forceinline__ float silu_mul(float g, float u) {
    return u * g / (1.f + __expf(-g));
}
__device__ __forceinline__ void mma16816(float d[4], uint32_t a0, uint32_t a1, uint32_t a2,
                                         uint32_t a3, uint32_t b0, uint32_t b1) {
    asm volatile(
        "mma.sync.aligned.m16n8k16.row.col.f32.f16.f16.f32 "
        "{%0,%1,%2,%3}, {%4,%5,%6,%7}, {%8,%9}, {%0,%1,%2,%3};"
        : "+f"(d[0]), "+f"(d[1]), "+f"(d[2]), "+f"(d[3])
        : "r"(a0), "r"(a1), "r"(a2), "r"(a3), "r"(b0), "r"(b1));
}
__device__ __forceinline__ void ldsm4(uint32_t r[4], uint32_t addr) {
    asm volatile("ldmatrix.sync.aligned.m8n8.x4.shared.b16 {%0,%1,%2,%3}, [%4];"
                 : "=r"(r[0]), "=r"(r[1]), "=r"(r[2]), "=r"(r[3]) : "r"(addr));
}

// ---------------- GEMM core: C[128x128] += A * B  (fp16 x fp16, f32 accum) ----------------
// 4 warps, 64x64 warp tiles. acc[4][8][4]. a_p/b_p: per-thread row pointers (row t).
__device__ __forceinline__ void gemm_core(const __half* __restrict__ a_p,
                                          const __half* __restrict__ b_p,
                                          int Ktot, char* sm, uint32_t sbu,
                                          float acc[4][8][4]) {
    const int t = threadIdx.x;
    const int lane = t & 31, wid = t >> 5;
    const int wm0 = (wid >> 1) * 64, wn0 = (wid & 1) * 64;
    const int nc = Ktot / KC;
    const int lrow = lane & 15, lhalf = lane >> 4;   // ldmatrix lane mapping

    const uint32_t sA = sbu + SM_A + t * A_PITCH;
    const uint32_t sB = sbu + SM_B + t * A_PITCH;
    const uint32_t lmA = sbu + SM_A + (wm0 + lrow) * A_PITCH + lhalf * 16;
    const uint32_t lmB = sbu + SM_B + (wn0 + lrow) * A_PITCH + lhalf * 16;

    // prologue: chunk 0 into stage 0 (one full 128B row per thread, A and B)
#pragma unroll
    for (int q = 0; q < 8; q++) {
        cpa16(sA + q * 16, a_p + q * 8);
        cpa16(sB + q * 16, b_p + q * 8);
    }
    cpa_commit();

    for (int c = 0; c < nc; c++) {
        const int s = c & 1;
        cpa_wait0();
        __syncthreads();
        if (c + 1 < nc) {
            const uint32_t so = (1 - s) * SM_STAGE;
            const __half* pa = a_p + (c + 1) * KC;
            const __half* pb = b_p + (c + 1) * KC;
#pragma unroll
            for (int q = 0; q < 8; q++) {
                cpa16(sA + so + q * 16, pa + q * 8);
                cpa16(sB + so + q * 16, pb + q * 8);
            }
            cpa_commit();
        }
        const uint32_t stA = lmA + s * SM_STAGE;
        const uint32_t stB = lmB + s * SM_STAGE;
#pragma unroll
        for (int ks = 0; ks < KC / 16; ks++) {
            uint32_t ah[4][4];
#pragma unroll
            for (int mi = 0; mi < 4; mi++)
                ldsm4(ah[mi], stA + mi * 16 * A_PITCH + ks * 32);
            uint32_t bb[4][4];
#pragma unroll
            for (int njp = 0; njp < 4; njp++)
                ldsm4(bb[njp], stB + njp * 16 * A_PITCH + ks * 32);
#pragma unroll
            for (int njp = 0; njp < 4; njp++)
#pragma unroll
                for (int sub = 0; sub < 2; sub++) {
                    int nj = njp * 2 + sub;
                    uint32_t b0 = bb[njp][sub];
                    uint32_t b1 = bb[njp][2 + sub];
#pragma unroll
                    for (int mi = 0; mi < 4; mi++)
                        mma16816(acc[mi][nj], ah[mi][0], ah[mi][1], ah[mi][2], ah[mi][3], b0, b1);
                }
        }
    }
}

// ---------------- vectorized transpose-convert (one 32x32 tile) ----------------
__device__ __forceinline__ void cvt4(const float* __restrict__ s, __half* __restrict__ oh,
                                     int K, int N, int remap_half, int bx, int by, int t,
                                     float tile[32][33]) {
    int c0 = bx * 32, k0 = by * 32;
    int k = t >> 3, c4 = (t & 7) << 2;
    float4 v = *(const float4*)&s[(size_t)(k0 + k) * N + c0 + c4];
    tile[k][c4]     = v.x;
    tile[k][c4 + 1] = v.y;
    tile[k][c4 + 2] = v.z;
    tile[k][c4 + 3] = v.w;
    __syncthreads();
    int nl = t >> 3, kq = (t & 7) << 2;
    int cc = c0 + nl;
    int n = remap_half ? (2 * (cc % remap_half) + cc / remap_half) : cc;
    __half2 h0 = __floats2half2_rn(tile[kq][nl], tile[kq + 1][nl]);
    __half2 h1 = __floats2half2_rn(tile[kq + 2][nl], tile[kq + 3][nl]);
    uint2 u;
    u.x = *(uint32_t*)&h0;
    u.y = *(uint32_t*)&h1;
    *(uint2*)&oh[(size_t)n * K + k0 + kq] = u;
}

// ---------------- merged prep: router + all weight conversions, one launch ----------------
__global__ __launch_bounds__(256) void k_prep(const float* __restrict__ x,
                                              const float* __restrict__ rw,
                                              float* __restrict__ out_logits,
                                              const float* __restrict__ gup,
                                              const float* __restrict__ dwn,
                                              const float* __restrict__ sgate,
                                              const float* __restrict__ sup,
                                              const float* __restrict__ sdown) {
    __shared__ float tile[32][33];
    int b = blockIdx.x, t = threadIdx.x;

    if (b < PREP_R) {
        // ---- router: 8 warps, 1 token each; fused x->fp16 ----
        int warp = t >> 5, lane = t & 31;
        int tok = b * 8 + warp;
        const float* xr = x + (size_t)tok * HDIM;
        __half* xo = g_x + (size_t)tok * HDIM;
        float acc[NE];
#pragma unroll
        for (int e = 0; e < NE; e++) acc[e] = 0.f;
        for (int i = lane; i < HDIM; i += 32) {
            float xv = xr[i];
            xo[i] = __float2half_rn(xv);
#pragma unroll
            for (int e = 0; e < NE; e++) acc[e] = fmaf(xv, rw[e * HDIM + i], acc[e]);
        }
#pragma unroll
        for (int e = 0; e < NE; e++) {
#pragma unroll
            for (int o = 16; o > 0; o >>= 1) acc[e] += __shfl_xor_sync(0xFFFFFFFFu, acc[e], o);
        }
        if (lane == 0) {
            if (out_logits) {
#pragma unroll
                for (int e = 0; e < NE; e++) out_logits[(size_t)tok * NE + e] = acc[e];
            }
            int e1 = 0; float v1 = acc[0];
#pragma unroll
            for (int e = 1; e < NE; e++) if (acc[e] > v1) { v1 = acc[e]; e1 = e; }
            int e2 = -1; float v2 = -1e30f;
#pragma unroll
            for (int e = 0; e < NE; e++) if (e != e1 && acc[e] > v2) { v2 = acc[e]; e2 = e; }
            g_tope[tok * 2 + 0] = e1; g_tops[tok * 2 + 0] = 1.f / (1.f + __expf(-v1));
            g_tope[tok * 2 + 1] = e2; g_tops[tok * 2 + 1] = 1.f / (1.f + __expf(-v2));
        }
    } else if (b < PREP_R + PREP_G) {
        int i = b - PREP_R;
        int bx = i & 127, by = (i >> 7) & 31, e = i >> 12;
        cvt4(gup + (size_t)e * HDIM * 2 * IDIM, g_wgu + (size_t)e * 2 * IDIM * HDIM,
             HDIM, 2 * IDIM, IDIM, bx, by, t, tile);
    } else if (b < PREP_R + PREP_G + PREP_D) {
        int i = b - PREP_R - PREP_G;
        int bx = i & 31, by = (i >> 5) & 63, e = i >> 11;
        cvt4(dwn + (size_t)e * IDIM * HDIM, g_wdn + (size_t)e * HDIM * IDIM,
             IDIM, HDIM, 0, bx, by, t, tile);
    } else {
        int i = b - PREP_R - PREP_G - PREP_D;
        size_t id = ((size_t)i * 256 + t) * 4;
        int j = (int)(id / HDIM), k = (int)(id % HDIM);
        float4 gv = *(const float4*)(sgate + id);
        float4 uv = *(const float4*)(sup + id);
        __half* dg = g_wsg + (size_t)(2 * j) * HDIM + k;
        __half* du = g_wsg + (size_t)(2 * j + 1) * HDIM + k;
        *(__half2*)(dg)     = __floats2half2_rn(gv.x, gv.y);
        *(__half2*)(dg + 2) = __floats2half2_rn(gv.z, gv.w);
        *(__half2*)(du)     = __floats2half2_rn(uv.x, uv.y);
        *(__half2*)(du + 2) = __floats2half2_rn(uv.z, uv.w);
        float4 v = *(const float4*)(sdown + id);
        *(__half2*)(g_wsd + id)     = __floats2half2_rn(v.x, v.y);
        *(__half2*)(g_wsd + id + 2) = __floats2half2_rn(v.z, v.w);
    }
}

// ---------------- single-CTA scatter: count + prefix + scatter ----------------
__global__ __launch_bounds__(1024) void k_scatter_all() {
    __shared__ int cnt[NE], off[NE], cur[NE];
    int tid = threadIdx.x;
    if (tid < NE) cnt[tid] = 0;
    __syncthreads();
    for (int p = tid; p < NPAIR; p += 1024)
        atomicAdd(&cnt[g_tope[p]], 1);
    __syncthreads();
    if (tid == 0) {
        int s = 0;
        for (int e = 0; e < NE; e++) { off[e] = s; s += cnt[e]; cur[e] = 0; }
    }
    __syncthreads();
    for (int p = tid; p < NPAIR; p += 1024) {
        int e = g_tope[p];
        int pos = atomicAdd(&cur[e], 1);
        int r = off[e] + pos;
        g_row_tok[r]  = p >> 1;
        g_row_sc[r]   = g_tops[p];
        g_row_slot[r] = p & 1;
    }
    if (tid < NE) { g_cnt[tid] = cnt[tid]; g_off[tid] = off[tid]; }
}

// ---------------- GEMM layer 1: routed gate_up (y<256) + shared gate_up (y>=256) ----------------
__global__ __launch_bounds__(GTHR, 2) void tc_l1() {
    extern __shared__ char sm[];
    uint32_t sbu = smem_u32(sm);
    int t = threadIdx.x;
    int lane = t & 31, wid = t >> 5, g = lane >> 2, tg = lane & 3;
    int wm0 = (wid >> 1) * 64, wn0 = (wid & 1) * 64;
    int n0 = blockIdx.x * 128;

    float acc[4][8][4];
#pragma unroll
    for (int a = 0; a < 4; a++)
#pragma unroll
        for (int b = 0; b < 8; b++)
#pragma unroll
            for (int q = 0; q < 4; q++) acc[a][b][q] = 0.f;

    int jb = n0 / 2 + wn0 / 2 + tg;

    if (blockIdx.y < 256) {
        // ---- routed gate_up ----
        int e = blockIdx.y >> 5, rt = blockIdx.y & 31;
        int cnt = g_cnt[e];
        int row0 = rt * 128;
        if (row0 >= cnt) return;
        int base = g_off[e];
        int rr = base + min(row0 + t, cnt - 1);
        const __half* ap = g_x + (size_t)g_row_tok[rr] * HDIM;
        const __half* bp = g_wgu + (size_t)e * 2 * IDIM * HDIM + (size_t)(n0 + t) * HDIM;

        gemm_core(ap, bp, HDIM, sm, sbu, acc);

#pragma unroll
        for (int mi = 0; mi < 4; mi++)
#pragma unroll
            for (int dq = 0; dq < 2; dq++) {
                int rl = wm0 + mi * 16 + g + dq * 8;
                if (row0 + rl < cnt) {
                    int grow = base + row0 + rl;
                    float sc = g_row_sc[grow];
                    __half* dh = g_act + (size_t)grow * IDIM;
#pragma unroll
                    for (int nj = 0; nj < 8; nj++) {
                        float v = silu_mul(sc * acc[mi][nj][dq * 2], sc * acc[mi][nj][dq * 2 + 1]);
                        dh[jb + nj * 4] = __float2half_rn(v);
                    }
                }
            }
    } else {
        // ---- shared gate_up ----
        int row0 = (blockIdx.y - 256) * 128;
        const __half* ap = g_x + (size_t)(row0 + t) * HDIM;
        const __half* bp = g_wsg + (size_t)(n0 + t) * HDIM;

        gemm_core(ap, bp, HDIM, sm, sbu, acc);

#pragma unroll
        for (int mi = 0; mi < 4; mi++)
#pragma unroll
            for (int dq = 0; dq < 2; dq++) {
                int rl = wm0 + mi * 16 + g + dq * 8;
                __half* dh = g_acts + (size_t)(row0 + rl) * IDIM;
#pragma unroll
                for (int nj = 0; nj < 8; nj++) {
                    float v = silu_mul(acc[mi][nj][dq * 2], acc[mi][nj][dq * 2 + 1]);
                    dh[jb + nj * 4] = __float2half_rn(v);
                }
            }
    }
}

// ---------------- GEMM layer 2: routed down ----------------
__global__ __launch_bounds__(GTHR, 2) void tc_dn_routed() {
    int e = blockIdx.y >> 5, rt = blockIdx.y & 31;
    int cnt = g_cnt[e];
    int row0 = rt * 128;
    if (row0 >= cnt) return;
    int base = g_off[e];

    extern __shared__ char sm[];
    uint32_t sbu = smem_u32(sm);
    int t = threadIdx.x;
    const __half* ap = g_act + (size_t)(base + min(row0 + t, cnt - 1)) * IDIM;
    int n0 = blockIdx.x * 128;
    const __half* bp = g_wdn + (size_t)e * HDIM * IDIM + (size_t)(n0 + t) * IDIM;

    float acc[4][8][4];
#pragma unroll
    for (int a = 0; a < 4; a++)
#pragma unroll
        for (int b = 0; b < 8; b++)
#pragma unroll
            for (int q = 0; q < 4; q++) acc[a][b][q] = 0.f;

    gemm_core(ap, bp, IDIM, sm, sbu, acc);

    int lane = t & 31, wid = t >> 5, g = lane >> 2, tg = lane & 3;
    int wm0 = (wid >> 1) * 64, wn0 = (wid & 1) * 64;
    int colb = n0 + wn0 + tg * 2;
#pragma unroll
    for (int mi = 0; mi < 4; mi++)
#pragma unroll
        for (int dq = 0; dq < 2; dq++) {
            int rl = wm0 + mi * 16 + g + dq * 8;
            if (row0 + rl < cnt) {
                int grow = base + row0 + rl;
                int tok = g_row_tok[grow], slot = g_row_slot[grow];
                float* dst = g_partial[slot] + (size_t)tok * HDIM;
#pragma unroll
                for (int nj = 0; nj < 8; nj++) {
                    float2 v = {acc[mi][nj][dq * 2], acc[mi][nj][dq * 2 + 1]};
                    *(float2*)&dst[colb + nj * 8] = v;
                }
            }
        }
}

// ---------------- GEMM layer 3: shared down + final add ----------------
__global__ __launch_bounds__(GTHR, 2) void tc_dn_shared(float* __restrict__ out) {
    int row0 = blockIdx.y * 128;
    int n0 = blockIdx.x * 128;

    extern __shared__ char sm[];
    uint32_t sbu = smem_u32(sm);
    int t = threadIdx.x;
    const __half* ap = g_acts + (size_t)(row0 + t) * IDIM;
    const __half* bp = g_wsd + (size_t)(n0 + t) * IDIM;

    float acc[4][8][4];
#pragma unroll
    for (int a = 0; a < 4; a++)
#pragma unroll
        for (int b = 0; b < 8; b++)
#pragma unroll
            for (int q = 0; q < 4; q++) acc[a][b][q] = 0.f;

    gemm_core(ap, bp, IDIM, sm, sbu, acc);

    int lane = t & 31, wid = t >> 5, g = lane >> 2, tg = lane & 3;
    int wm0 = (wid >> 1) * 64, wn0 = (wid & 1) * 64;
    int colb = n0 + wn0 + tg * 2;
#pragma unroll
    for (int mi = 0; mi < 4; mi++)
#pragma unroll
        for (int dq = 0; dq < 2; dq++) {
            int row = row0 + wm0 + mi * 16 + g + dq * 8;
            size_t rbase = (size_t)row * HDIM;
#pragma unroll
            for (int nj = 0; nj < 8; nj++) {
                size_t idx = rbase + colb + nj * 8;
                float2 p0 = *(const float2*)&g_partial[0][idx];
                float2 p1 = *(const float2*)&g_partial[1][idx];
                float2 v;
                v.x = acc[mi][nj][dq * 2] + p0.x + p1.x;
                v.y = acc[mi][nj][dq * 2 + 1] + p0.y + p1.y;
                *(float2*)&out[idx] = v;
            }
        }
}

// ---------------- launch ----------------
extern "C" void kernel_launch(void* const* d_in, const int* in_sizes, int n_in,
                              void* d_out, int out_size) {
    const float* x     = (const float*)d_in[0];   // [T, H]
    const float* rw    = (const float*)d_in[1];   // [E, H]
    const float* gup   = (const float*)d_in[2];   // [E, H, 2I]
    const float* dwn   = (const float*)d_in[3];   // [E, I, H]
    const float* sgate = (const float*)d_in[4];   // [I, H]
    const float* sup   = (const float*)d_in[5];   // [I, H]
    const float* sdown = (const float*)d_in[6];   // [H, I]
    float* out = (float*)d_out;

    float* out_logits = nullptr;
    if (out_size >= TTOK * HDIM + TTOK * NE) out_logits = out + (size_t)TTOK * HDIM;

    cudaFuncSetAttribute(tc_l1,        cudaFuncAttributeMaxDynamicSharedMemorySize, SMEM_GEMM);
    cudaFuncSetAttribute(tc_dn_routed, cudaFuncAttributeMaxDynamicSharedMemorySize, SMEM_GEMM);
    cudaFuncSetAttribute(tc_dn_shared, cudaFuncAttributeMaxDynamicSharedMemorySize, SMEM_GEMM);

    k_prep<<<PREP_TOTAL, 256>>>(x, rw, out_logits, gup, dwn, sgate, sup, sdown);
    k_scatter_all<<<1, 1024>>>();

    tc_l1<<<dim3(2 * IDIM / 128, 256 + TTOK / 128), GTHR, SMEM_GEMM>>>();
    tc_dn_routed<<<dim3(HDIM / 128, NE * 32), GTHR, SMEM_GEMM>>>();
    tc_dn_shared<<<dim3(HDIM / 128, TTOK / 128), GTHR, SMEM_GEMM>>>(out);
}

// round 14
// speedup vs baseline: 1.0218x; 1.0218x over previous
#include <cuda_runtime.h>
#include <cuda_fp16.h>
#include <stdint.h>
#include <math.h>

// Problem constants
#define TTOK 4096
#define HDIM 1024
#define IDIM 2048
#define NE   8
#define NPAIR (TTOK * 2)

// GEMM config: 128x128 CTA tile, 8 warps (4M x 2N of 32x64), KC=64, 3-stage pipeline
#define KC 64
#define A_PITCH 144              // bytes per smem row (64 fp16 + pad; ldmatrix conflict-free)
#define SM_A 0
#define SM_B (128 * A_PITCH)                 // 18432
#define SM_STAGE (2 * 128 * A_PITCH)         // 36864
#define NSTAGE 3
#define SMEM_GEMM (NSTAGE * SM_STAGE)        // 110592 -> 2 CTAs/SM (221KB < 228KB)

// prep-kernel job ranges
#define PREP_R 512                            // router: 8 tokens/block
#define PREP_G 32768                          // gup transpose: 128 x 32 x 8
#define PREP_D 16384                          // dwn transpose: 32 x 64 x 8
#define PREP_S 2048                           // shared cvt: (I*H)/1024
#define PREP_TOTAL (PREP_R + PREP_G + PREP_D + PREP_S)

// ---------------- scratch (static __device__ — no allocation) ----------------
__device__ __half g_x[(size_t)TTOK * HDIM];             // x fp16 (written by router)
__device__ __half g_act[(size_t)NPAIR * IDIM];          // routed swiglu act fp16
__device__ __half g_acts[(size_t)TTOK * IDIM];          // shared swiglu act fp16
__device__ float g_partial[2][(size_t)TTOK * HDIM];     // per-slot routed outputs
__device__ int   g_row_tok[NPAIR];
__device__ float g_row_sc[NPAIR];
__device__ int   g_row_slot[NPAIR];
__device__ int   g_tope[NPAIR];
__device__ float g_tops[NPAIR];
__device__ int   g_cnt[NE];
__device__ int   g_off[NE];

// fp16 weights, [n][k] col-major-for-mma layouts
__device__ __half g_wgu[(size_t)NE * 2 * IDIM * HDIM];   // interleaved gate/up rows
__device__ __half g_wdn[(size_t)NE * HDIM * IDIM];       // [H][I]
__device__ __half g_wsg[(size_t)2 * IDIM * HDIM];        // shared gate/up interleaved
__device__ __half g_wsd[(size_t)HDIM * IDIM];            // [H][I]

// ---------------- small helpers ----------------
__device__ __forceinline__ uint32_t smem_u32(const void* p) {
    uint32_t a;
    asm("{ .reg .u64 t; cvta.to.shared.u64 t, %1; cvt.u32.u64 %0, t; }" : "=r"(a) : "l"(p));
    return a;
}
__device__ __forceinline__ void cpa16(uint32_t saddr, const void* g) {
    asm volatile("cp.async.ca.shared.global [%0], [%1], 16;" :: "r"(saddr), "l"(g));
}
__device__ __forceinline__ void cpa_commit() {
    asm volatile("cp.async.commit_group;" ::: "memory");
}
__device__ __forceinline__ void cpa_wait0() {
    asm volatile("cp.async.wait_group 0;" ::: "memory");
}
__device__ __forceinline__ void cpa_wait1() {
    asm volatile("cp.async.wait_group 1;" ::: "memory");
}
__device__ __forceinline__ float silu_mul(float g, float u) {
    return u * g / (1.f + __expf(-g));
}
__device__ __forceinline__ void mma16816(float d[4], uint32_t a0, uint32_t a1, uint32_t a2,
                                         uint32_t a3, uint32_t b0, uint32_t b1) {
    asm volatile(
        "mma.sync.aligned.m16n8k16.row.col.f32.f16.f16.f32 "
        "{%0,%1,%2,%3}, {%4,%5,%6,%7}, {%8,%9}, {%0,%1,%2,%3};"
        : "+f"(d[0]), "+f"(d[1]), "+f"(d[2]), "+f"(d[3])
        : "r"(a0), "r"(a1), "r"(a2), "r"(a3), "r"(b0), "r"(b1));
}
__device__ __forceinline__ void ldsm4(uint32_t r[4], uint32_t addr) {
    asm volatile("ldmatrix.sync.aligned.m8n8.x4.shared.b16 {%0,%1,%2,%3}, [%4];"
                 : "=r"(r[0]), "=r"(r[1]), "=r"(r[2]), "=r"(r[3]) : "r"(addr));
}

// ---------------- GEMM core: C[128x128] += A * B  (fp16 x fp16, f32 accum) ----------------
// 8 warps (4M x 2N), 32x64 warp tiles, ldmatrix frags, 3-stage cp.async pipeline.
__device__ __forceinline__ void gemm_core(const __half* __restrict__ a_p,
                                          const __half* __restrict__ b_p,
                                          int Ktot, char* sm, uint32_t sbu,
                                          float acc[2][8][4]) {
    const int t = threadIdx.x;
    const int lane = t & 31, wid = t >> 5;
    const int wm0 = (wid >> 1) * 32, wn0 = (wid & 1) * 64;
    const int nc = Ktot / KC;
    const int lrow = lane & 15, lhalf = lane >> 4;   // ldmatrix lane mapping

    const uint32_t sA = sbu + SM_A + (t >> 1) * A_PITCH + (t & 1) * 64;
    const uint32_t sB = sbu + SM_B + (t >> 1) * A_PITCH + (t & 1) * 64;
    const uint32_t lmA = sbu + SM_A + (wm0 + lrow) * A_PITCH + lhalf * 16;
    const uint32_t lmB = sbu + SM_B + (wn0 + lrow) * A_PITCH + lhalf * 16;

    // prologue: chunks 0 and 1 into stages 0 and 1 (separate groups)
#pragma unroll
    for (int q = 0; q < 4; q++) {
        cpa16(sA + q * 16, a_p + q * 8);
        cpa16(sB + q * 16, b_p + q * 8);
    }
    cpa_commit();
    if (1 < nc) {
#pragma unroll
        for (int q = 0; q < 4; q++) {
            cpa16(sA + SM_STAGE + q * 16, a_p + KC + q * 8);
            cpa16(sB + SM_STAGE + q * 16, b_p + KC + q * 8);
        }
    }
    cpa_commit();

    int s = 0;
    for (int c = 0; c < nc; c++) {
        if (c + 1 < nc) cpa_wait1(); else cpa_wait0();
        __syncthreads();
        if (c + 2 < nc) {
            int s2 = s + 2; if (s2 >= NSTAGE) s2 -= NSTAGE;
            const uint32_t so = s2 * SM_STAGE;
            const __half* pa = a_p + (c + 2) * KC;
            const __half* pb = b_p + (c + 2) * KC;
#pragma unroll
            for (int q = 0; q < 4; q++) {
                cpa16(sA + so - 0 * SM_STAGE + q * 16 + (so - (sA - sA)) * 0, pa + q * 8);
                cpa16(sB + so + q * 16, pb + q * 8);
            }
            cpa_commit();
        }
        const uint32_t stA = lmA + s * SM_STAGE;
        const uint32_t stB = lmB + s * SM_STAGE;
#pragma unroll
        for (int ks = 0; ks < KC / 16; ks++) {
            uint32_t ah[2][4];
#pragma unroll
            for (int mi = 0; mi < 2; mi++)
                ldsm4(ah[mi], stA + mi * 16 * A_PITCH + ks * 32);
            uint32_t bb[4][4];
#pragma unroll
            for (int njp = 0; njp < 4; njp++)
                ldsm4(bb[njp], stB + njp * 16 * A_PITCH + ks * 32);
#pragma unroll
            for (int njp = 0; njp < 4; njp++)
#pragma unroll
                for (int sub = 0; sub < 2; sub++) {
                    int nj = njp * 2 + sub;
                    uint32_t b0 = bb[njp][sub];
                    uint32_t b1 = bb[njp][2 + sub];
#pragma unroll
                    for (int mi = 0; mi < 2; mi++)
                        mma16816(acc[mi][nj], ah[mi][0], ah[mi][1], ah[mi][2], ah[mi][3], b0, b1);
                }
        }
        s++; if (s >= NSTAGE) s = 0;
    }
}

// NOTE: the weird arithmetic in the A prefetch above must be a clean store; fix inline:
// (kept simple below via corrected body — see gemm_core2 used by all kernels)
__device__ __forceinline__ void gemm_core2(const __half* __restrict__ a_p,
                                           const __half* __restrict__ b_p,
                                           int Ktot, char* sm, uint32_t sbu,
                                           float acc[2][8][4]) {
    const int t = threadIdx.x;
    const int lane = t & 31, wid = t >> 5;
    const int wm0 = (wid >> 1) * 32, wn0 = (wid & 1) * 64;
    const int nc = Ktot / KC;
    const int lrow = lane & 15, lhalf = lane >> 4;

    const uint32_t sA = sbu + SM_A + (t >> 1) * A_PITCH + (t & 1) * 64;
    const uint32_t sB = sbu + SM_B + (t >> 1) * A_PITCH + (t & 1) * 64;
    const uint32_t lmA = sbu + SM_A + (wm0 + lrow) * A_PITCH + lhalf * 16;
    const uint32_t lmB = sbu + SM_B + (wn0 + lrow) * A_PITCH + lhalf * 16;

#pragma unroll
    for (int q = 0; q < 4; q++) {
        cpa16(sA + q * 16, a_p + q * 8);
        cpa16(sB + q * 16, b_p + q * 8);
    }
    cpa_commit();
    if (1 < nc) {
#pragma unroll
        for (int q = 0; q < 4; q++) {
            cpa16(sA + SM_STAGE + q * 16, a_p + KC + q * 8);
            cpa16(sB + SM_STAGE + q * 16, b_p + KC + q * 8);
        }
    }
    cpa_commit();

    int s = 0;
    for (int c = 0; c < nc; c++) {
        if (c + 1 < nc) cpa_wait1(); else cpa_wait0();
        __syncthreads();
        if (c + 2 < nc) {
            int s2 = s + 2; if (s2 >= NSTAGE) s2 -= NSTAGE;
            const uint32_t so = s2 * SM_STAGE;
            const __half* pa = a_p + (c + 2) * KC;
            const __half* pb = b_p + (c + 2) * KC;
#pragma unroll
            for (int q = 0; q < 4; q++) {
                cpa16(sA + so + q * 16, pa + q * 8);
                cpa16(sB + so + q * 16, pb + q * 8);
            }
            cpa_commit();
        }
        const uint32_t stA = lmA + s * SM_STAGE;
        const uint32_t stB = lmB + s * SM_STAGE;
#pragma unroll
        for (int ks = 0; ks < KC / 16; ks++) {
            uint32_t ah[2][4];
#pragma unroll
            for (int mi = 0; mi < 2; mi++)
                ldsm4(ah[mi], stA + mi * 16 * A_PITCH + ks * 32);
            uint32_t bb[4][4];
#pragma unroll
            for (int njp = 0; njp < 4; njp++)
                ldsm4(bb[njp], stB + njp * 16 * A_PITCH + ks * 32);
#pragma unroll
            for (int njp = 0; njp < 4; njp++)
#pragma unroll
                for (int sub = 0; sub < 2; sub++) {
                    int nj = njp * 2 + sub;
                    uint32_t b0 = bb[njp][sub];
                    uint32_t b1 = bb[njp][2 + sub];
#pragma unroll
                    for (int mi = 0; mi < 2; mi++)
                        mma16816(acc[mi][nj], ah[mi][0], ah[mi][1], ah[mi][2], ah[mi][3], b0, b1);
                }
        }
        s++; if (s >= NSTAGE) s = 0;
    }
}

// ---------------- vectorized transpose-convert (one 32x32 tile) ----------------
__device__ __forceinline__ void cvt4(const float* __restrict__ s, __half* __restrict__ oh,
                                     int K, int N, int remap_half, int bx, int by, int t,
                                     float tile[32][33]) {
    int c0 = bx * 32, k0 = by * 32;
    int k = t >> 3, c4 = (t & 7) << 2;
    float4 v = *(const float4*)&s[(size_t)(k0 + k) * N + c0 + c4];
    tile[k][c4]     = v.x;
    tile[k][c4 + 1] = v.y;
    tile[k][c4 + 2] = v.z;
    tile[k][c4 + 3] = v.w;
    __syncthreads();
    int nl = t >> 3, kq = (t & 7) << 2;
    int cc = c0 + nl;
    int n = remap_half ? (2 * (cc % remap_half) + cc / remap_half) : cc;
    __half2 h0 = __floats2half2_rn(tile[kq][nl], tile[kq + 1][nl]);
    __half2 h1 = __floats2half2_rn(tile[kq + 2][nl], tile[kq + 3][nl]);
    uint2 u;
    u.x = *(uint32_t*)&h0;
    u.y = *(uint32_t*)&h1;
    *(uint2*)&oh[(size_t)n * K + k0 + kq] = u;
}

// ---------------- merged prep: router + all weight conversions, one launch ----------------
__global__ __launch_bounds__(256) void k_prep(const float* __restrict__ x,
                                              const float* __restrict__ rw,
                                              float* __restrict__ out_logits,
                                              const float* __restrict__ gup,
                                              const float* __restrict__ dwn,
                                              const float* __restrict__ sgate,
                                              const float* __restrict__ sup,
                                              const float* __restrict__ sdown) {
    __shared__ float tile[32][33];
    int b = blockIdx.x, t = threadIdx.x;

    if (b < PREP_R) {
        int warp = t >> 5, lane = t & 31;
        int tok = b * 8 + warp;
        const float* xr = x + (size_t)tok * HDIM;
        __half* xo = g_x + (size_t)tok * HDIM;
        float acc[NE];
#pragma unroll
        for (int e = 0; e < NE; e++) acc[e] = 0.f;
        for (int i = lane; i < HDIM; i += 32) {
            float xv = xr[i];
            xo[i] = __float2half_rn(xv);
#pragma unroll
            for (int e = 0; e < NE; e++) acc[e] = fmaf(xv, rw[e * HDIM + i], acc[e]);
        }
#pragma unroll
        for (int e = 0; e < NE; e++) {
#pragma unroll
            for (int o = 16; o > 0; o >>= 1) acc[e] += __shfl_xor_sync(0xFFFFFFFFu, acc[e], o);
        }
        if (lane == 0) {
            if (out_logits) {
#pragma unroll
                for (int e = 0; e < NE; e++) out_logits[(size_t)tok * NE + e] = acc[e];
            }
            int e1 = 0; float v1 = acc[0];
#pragma unroll
            for (int e = 1; e < NE; e++) if (acc[e] > v1) { v1 = acc[e]; e1 = e; }
            int e2 = -1; float v2 = -1e30f;
#pragma unroll
            for (int e = 0; e < NE; e++) if (e != e1 && acc[e] > v2) { v2 = acc[e]; e2 = e; }
            g_tope[tok * 2 + 0] = e1; g_tops[tok * 2 + 0] = 1.f / (1.f + __expf(-v1));
            g_tope[tok * 2 + 1] = e2; g_tops[tok * 2 + 1] = 1.f / (1.f + __expf(-v2));
        }
    } else if (b < PREP_R + PREP_G) {
        int i = b - PREP_R;
        int bx = i & 127, by = (i >> 7) & 31, e = i >> 12;
        cvt4(gup + (size_t)e * HDIM * 2 * IDIM, g_wgu + (size_t)e * 2 * IDIM * HDIM,
             HDIM, 2 * IDIM, IDIM, bx, by, t, tile);
    } else if (b < PREP_R + PREP_G + PREP_D) {
        int i = b - PREP_R - PREP_G;
        int bx = i & 31, by = (i >> 5) & 63, e = i >> 11;
        cvt4(dwn + (size_t)e * IDIM * HDIM, g_wdn + (size_t)e * HDIM * IDIM,
             IDIM, HDIM, 0, bx, by, t, tile);
    } else {
        int i = b - PREP_R - PREP_G - PREP_D;
        size_t id = ((size_t)i * 256 + t) * 4;
        int j = (int)(id / HDIM), k = (int)(id % HDIM);
        float4 gv = *(const float4*)(sgate + id);
        float4 uv = *(const float4*)(sup + id);
        __half* dg = g_wsg + (size_t)(2 * j) * HDIM + k;
        __half* du = g_wsg + (size_t)(2 * j + 1) * HDIM + k;
        *(__half2*)(dg)     = __floats2half2_rn(gv.x, gv.y);
        *(__half2*)(dg + 2) = __floats2half2_rn(gv.z, gv.w);
        *(__half2*)(du)     = __floats2half2_rn(uv.x, uv.y);
        *(__half2*)(du + 2) = __floats2half2_rn(uv.z, uv.w);
        float4 v = *(const float4*)(sdown + id);
        *(__half2*)(g_wsd + id)     = __floats2half2_rn(v.x, v.y);
        *(__half2*)(g_wsd + id + 2) = __floats2half2_rn(v.z, v.w);
    }
}

// ---------------- single-CTA scatter: count + prefix + scatter ----------------
__global__ __launch_bounds__(1024) void k_scatter_all() {
    __shared__ int cnt[NE], off[NE], cur[NE];
    int tid = threadIdx.x;
    if (tid < NE) cnt[tid] = 0;
    __syncthreads();
    for (int p = tid; p < NPAIR; p += 1024)
        atomicAdd(&cnt[g_tope[p]], 1);
    __syncthreads();
    if (tid == 0) {
        int s = 0;
        for (int e = 0; e < NE; e++) { off[e] = s; s += cnt[e]; cur[e] = 0; }
    }
    __syncthreads();
    for (int p = tid; p < NPAIR; p += 1024) {
        int e = g_tope[p];
        int pos = atomicAdd(&cur[e], 1);
        int r = off[e] + pos;
        g_row_tok[r]  = p >> 1;
        g_row_sc[r]   = g_tops[p];
        g_row_slot[r] = p & 1;
    }
    if (tid < NE) { g_cnt[tid] = cnt[tid]; g_off[tid] = off[tid]; }
}

// ---------------- GEMM layer 1: routed gate_up (y<256) + shared gate_up (y>=256) ----------------
__global__ __launch_bounds__(256, 2) void tc_l1() {
    extern __shared__ char sm[];
    uint32_t sbu = smem_u32(sm);
    int t = threadIdx.x;
    int lane = t & 31, wid = t >> 5, g = lane >> 2, tg = lane & 3;
    int wm0 = (wid >> 1) * 32, wn0 = (wid & 1) * 64;
    int n0 = blockIdx.x * 128;
    int rb = t >> 1, half = t & 1;

    float acc[2][8][4];
#pragma unroll
    for (int a = 0; a < 2; a++)
#pragma unroll
        for (int b = 0; b < 8; b++)
#pragma unroll
            for (int q = 0; q < 4; q++) acc[a][b][q] = 0.f;

    int jb = n0 / 2 + wn0 / 2 + tg;

    if (blockIdx.y < 256) {
        int e = blockIdx.y >> 5, rt = blockIdx.y & 31;
        int cnt = g_cnt[e];
        int row0 = rt * 128;
        if (row0 >= cnt) return;
        int base = g_off[e];
        int rr = base + min(row0 + rb, cnt - 1);
        const __half* ap = g_x + (size_t)g_row_tok[rr] * HDIM + half * 32;
        const __half* bp = g_wgu + (size_t)e * 2 * IDIM * HDIM + (size_t)(n0 + rb) * HDIM + half * 32;

        gemm_core2(ap, bp, HDIM, sm, sbu, acc);

#pragma unroll
        for (int mi = 0; mi < 2; mi++)
#pragma unroll
            for (int dq = 0; dq < 2; dq++) {
                int rl = wm0 + mi * 16 + g + dq * 8;
                if (row0 + rl < cnt) {
                    int grow = base + row0 + rl;
                    float sc = g_row_sc[grow];
                    __half* dh = g_act + (size_t)grow * IDIM;
#pragma unroll
                    for (int nj = 0; nj < 8; nj++) {
                        float v = silu_mul(sc * acc[mi][nj][dq * 2], sc * acc[mi][nj][dq * 2 + 1]);
                        dh[jb + nj * 4] = __float2half_rn(v);
                    }
                }
            }
    } else {
        int row0 = (blockIdx.y - 256) * 128;
        const __half* ap = g_x + (size_t)(row0 + rb) * HDIM + half * 32;
        const __half* bp = g_wsg + (size_t)(n0 + rb) * HDIM + half * 32;

        gemm_core2(ap, bp, HDIM, sm, sbu, acc);

#pragma unroll
        for (int mi = 0; mi < 2; mi++)
#pragma unroll
            for (int dq = 0; dq < 2; dq++) {
                int rl = wm0 + mi * 16 + g + dq * 8;
                __half* dh = g_acts + (size_t)(row0 + rl) * IDIM;
#pragma unroll
                for (int nj = 0; nj < 8; nj++) {
                    float v = silu_mul(acc[mi][nj][dq * 2], acc[mi][nj][dq * 2 + 1]);
                    dh[jb + nj * 4] = __float2half_rn(v);
                }
            }
    }
}

// ---------------- GEMM layer 2: routed down ----------------
__global__ __launch_bounds__(256, 2) void tc_dn_routed() {
    int e = blockIdx.y >> 5, rt = blockIdx.y & 31;
    int cnt = g_cnt[e];
    int row0 = rt * 128;
    if (row0 >= cnt) return;
    int base = g_off[e];

    extern __shared__ char sm[];
    uint32_t sbu = smem_u32(sm);
    int t = threadIdx.x, rb = t >> 1, half = t & 1;
    const __half* ap = g_act + (size_t)(base + min(row0 + rb, cnt - 1)) * IDIM + half * 32;
    int n0 = blockIdx.x * 128;
    const __half* bp = g_wdn + (size_t)e * HDIM * IDIM + (size_t)(n0 + rb) * IDIM + half * 32;

    float acc[2][8][4];
#pragma unroll
    for (int a = 0; a < 2; a++)
#pragma unroll
        for (int b = 0; b < 8; b++)
#pragma unroll
            for (int q = 0; q < 4; q++) acc[a][b][q] = 0.f;

    gemm_core2(ap, bp, IDIM, sm, sbu, acc);

    int lane = t & 31, wid = t >> 5, g = lane >> 2, tg = lane & 3;
    int wm0 = (wid >> 1) * 32, wn0 = (wid & 1) * 64;
    int colb = n0 + wn0 + tg * 2;
#pragma unroll
    for (int mi = 0; mi < 2; mi++)
#pragma unroll
        for (int dq = 0; dq < 2; dq++) {
            int rl = wm0 + mi * 16 + g + dq * 8;
            if (row0 + rl < cnt) {
                int grow = base + row0 + rl;
                int tok = g_row_tok[grow], slot = g_row_slot[grow];
                float* dst = g_partial[slot] + (size_t)tok * HDIM;
#pragma unroll
                for (int nj = 0; nj < 8; nj++) {
                    float2 v = {acc[mi][nj][dq * 2], acc[mi][nj][dq * 2 + 1]};
                    *(float2*)&dst[colb + nj * 8] = v;
                }
            }
        }
}

// ---------------- GEMM layer 3: shared down + final add ----------------
__global__ __launch_bounds__(256, 2) void tc_dn_shared(float* __restrict__ out) {
    int row0 = blockIdx.y * 128;
    int n0 = blockIdx.x * 128;

    extern __shared__ char sm[];
    uint32_t sbu = smem_u32(sm);
    int t = threadIdx.x, rb = t >> 1, half = t & 1;
    const __half* ap = g_acts + (size_t)(row0 + rb) * IDIM + half * 32;
    const __half* bp = g_wsd + (size_t)(n0 + rb) * IDIM + half * 32;

    float acc[2][8][4];
#pragma unroll
    for (int a = 0; a < 2; a++)
#pragma unroll
        for (int b = 0; b < 8; b++)
#pragma unroll
            for (int q = 0; q < 4; q++) acc[a][b][q] = 0.f;

    gemm_core2(ap, bp, IDIM, sm, sbu, acc);

    int lane = t & 31, wid = t >> 5, g = lane >> 2, tg = lane & 3;
    int wm0 = (wid >> 1) * 32, wn0 = (wid & 1) * 64;
    int colb = n0 + wn0 + tg * 2;
#pragma unroll
    for (int mi = 0; mi < 2; mi++)
#pragma unroll
        for (int dq = 0; dq < 2; dq++) {
            int row = row0 + wm0 + mi * 16 + g + dq * 8;
            size_t rbase = (size_t)row * HDIM;
#pragma unroll
            for (int nj = 0; nj < 8; nj++) {
                size_t idx = rbase + colb + nj * 8;
                float2 p0 = *(const float2*)&g_partial[0][idx];
                float2 p1 = *(const float2*)&g_partial[1][idx];
                float2 v;
                v.x = acc[mi][nj][dq * 2] + p0.x + p1.x;
                v.y = acc[mi][nj][dq * 2 + 1] + p0.y + p1.y;
                *(float2*)&out[idx] = v;
            }
        }
}

// ---------------- launch ----------------
extern "C" void kernel_launch(void* const* d_in, const int* in_sizes, int n_in,
                              void* d_out, int out_size) {
    const float* x     = (const float*)d_in[0];   // [T, H]
    const float* rw    = (const float*)d_in[1];   // [E, H]
    const float* gup   = (const float*)d_in[2];   // [E, H, 2I]
    const float* dwn   = (const float*)d_in[3];   // [E, I, H]
    const float* sgate = (const float*)d_in[4];   // [I, H]
    const float* sup   = (const float*)d_in[5];   // [I, H]
    const float* sdown = (const float*)d_in[6];   // [H, I]
    float* out = (float*)d_out;

    float* out_logits = nullptr;
    if (out_size >= TTOK * HDIM + TTOK * NE) out_logits = out + (size_t)TTOK * HDIM;

    cudaFuncSetAttribute(tc_l1,        cudaFuncAttributeMaxDynamicSharedMemorySize, SMEM_GEMM);
    cudaFuncSetAttribute(tc_dn_routed, cudaFuncAttributeMaxDynamicSharedMemorySize, SMEM_GEMM);
    cudaFuncSetAttribute(tc_dn_shared, cudaFuncAttributeMaxDynamicSharedMemorySize, SMEM_GEMM);

    k_prep<<<PREP_TOTAL, 256>>>(x, rw, out_logits, gup, dwn, sgate, sup, sdown);
    k_scatter_all<<<1, 1024>>>();

    tc_l1<<<dim3(2 * IDIM / 128, 256 + TTOK / 128), 256, SMEM_GEMM>>>();
    tc_dn_routed<<<dim3(HDIM / 128, NE * 32), 256, SMEM_GEMM>>>();
    tc_dn_shared<<<dim3(HDIM / 128, TTOK / 128), 256, SMEM_GEMM>>>(out);
}

// round 15
// speedup vs baseline: 1.3141x; 1.2861x over previous
#include <cuda_runtime.h>
#include <cuda_fp16.h>
#include <stdint.h>
#include <math.h>

// Problem constants
#define TTOK 4096
#define HDIM 1024
#define IDIM 2048
#define NE   8
#define NPAIR (TTOK * 2)

// GEMM config: 128x128 CTA tile, 8 warps (4M x 2N of 32x64), KC=64, double-buffered
#define KC 64
#define A_PITCH 144              // bytes per smem row (64 fp16 + pad; ldmatrix conflict-free)
#define SM_A 0
#define SM_B (128 * A_PITCH)                 // 18432
#define SM_STAGE (2 * 128 * A_PITCH)         // 36864
#define SMEM_GEMM (2 * SM_STAGE)             // 73728 -> 2 CTAs/SM

// prep-kernel job ranges
#define PREP_R 512                            // router: 8 tokens/block
#define PREP_G 32768                          // gup transpose: 128 x 32 x 8
#define PREP_D 16384                          // dwn transpose: 32 x 64 x 8
#define PREP_S 2048                           // shared cvt: (I*H)/1024
#define PREP_TOTAL (PREP_R + PREP_G + PREP_D + PREP_S)

// ---------------- scratch (static __device__ — no allocation) ----------------
__device__ __half g_x[(size_t)TTOK * HDIM];             // x fp16 (written by router)
__device__ __half g_act[(size_t)NPAIR * IDIM];          // routed swiglu act fp16
__device__ __half g_acts[(size_t)TTOK * IDIM];          // shared swiglu act fp16
__device__ float g_partial[2][(size_t)TTOK * HDIM];     // per-slot routed outputs
__device__ int   g_row_tok[NPAIR];
__device__ float g_row_sc[NPAIR];
__device__ int   g_row_slot[NPAIR];
__device__ int   g_tope[NPAIR];
__device__ float g_tops[NPAIR];
__device__ int   g_cnt[NE];
__device__ int   g_off[NE];

// fp16 weights, [n][k] col-major-for-mma layouts
__device__ __half g_wgu[(size_t)NE * 2 * IDIM * HDIM];   // interleaved gate/up rows
__device__ __half g_wdn[(size_t)NE * HDIM * IDIM];       // [H][I]
__device__ __half g_wsg[(size_t)2 * IDIM * HDIM];        // shared gate/up interleaved
__device__ __half g_wsd[(size_t)HDIM * IDIM];            // [H][I]

// ---------------- small helpers ----------------
__device__ __forceinline__ uint32_t smem_u32(const void* p) {
    uint32_t a;
    asm("{ .reg .u64 t; cvta.to.shared.u64 t, %1; cvt.u32.u64 %0, t; }" : "=r"(a) : "l"(p));
    return a;
}
__device__ __forceinline__ void cpa16(uint32_t saddr, const void* g) {
    asm volatile("cp.async.ca.shared.global [%0], [%1], 16;" :: "r"(saddr), "l"(g));
}
__device__ __forceinline__ void cpa16cg(uint32_t saddr, const void* g) {
    asm volatile("cp.async.cg.shared.global [%0], [%1], 16;" :: "r"(saddr), "l"(g));
}
__device__ __forceinline__ void cpa_commit() {
    asm volatile("cp.async.commit_group;" ::: "memory");
}
__device__ __forceinline__ void cpa_wait0() {
    asm volatile("cp.async.wait_group 0;" ::: "memory");
}
__device__ __forceinline__ float silu_mul(float g, float u) {
    return u * g / (1.f + __expf(-g));
}
__device__ __forceinline__ void mma16816(float d[4], uint32_t a0, uint32_t a1, uint32_t a2,
                                         uint32_t a3, uint32_t b0, uint32_t b1) {
    asm volatile(
        "mma.sync.aligned.m16n8k16.row.col.f32.f16.f16.f32 "
        "{%0,%1,%2,%3}, {%4,%5,%6,%7}, {%8,%9}, {%0,%1,%2,%3};"
        : "+f"(d[0]), "+f"(d[1]), "+f"(d[2]), "+f"(d[3])
        : "r"(a0), "r"(a1), "r"(a2), "r"(a3), "r"(b0), "r"(b1));
}
__device__ __forceinline__ void ldsm4(uint32_t r[4], uint32_t addr) {
    asm volatile("ldmatrix.sync.aligned.m8n8.x4.shared.b16 {%0,%1,%2,%3}, [%4];"
                 : "=r"(r[0]), "=r"(r[1]), "=r"(r[2]), "=r"(r[3]) : "r"(addr));
}

// ---------------- GEMM core: C[128x128] += A * B  (fp16 x fp16, f32 accum) ----------------
// 8 warps (4M x 2N), 32x64 warp tiles, ldmatrix frags, 2-stage cp.async pipeline.
// A loads via .ca (L1-resident, reused), B loads via .cg (streamed, L2 only).
__device__ __forceinline__ void gemm_core(const __half* __restrict__ a_p,
                                          const __half* __restrict__ b_p,
                                          int Ktot, char* sm, uint32_t sbu,
                                          float acc[2][8][4]) {
    const int t = threadIdx.x;
    const int lane = t & 31, wid = t >> 5;
    const int wm0 = (wid >> 1) * 32, wn0 = (wid & 1) * 64;
    const int nc = Ktot / KC;
    const int lrow = lane & 15, lhalf = lane >> 4;   // ldmatrix lane mapping

    const uint32_t sA = sbu + SM_A + (t >> 1) * A_PITCH + (t & 1) * 64;
    const uint32_t sB = sbu + SM_B + (t >> 1) * A_PITCH + (t & 1) * 64;
    const uint32_t lmA = sbu + SM_A + (wm0 + lrow) * A_PITCH + lhalf * 16;
    const uint32_t lmB = sbu + SM_B + (wn0 + lrow) * A_PITCH + lhalf * 16;

    // prologue: chunk 0 into stage 0
#pragma unroll
    for (int q = 0; q < 4; q++) {
        cpa16(sA + q * 16, a_p + q * 8);
        cpa16cg(sB + q * 16, b_p + q * 8);
    }
    cpa_commit();

    for (int c = 0; c < nc; c++) {
        const int s = c & 1;
        cpa_wait0();
        __syncthreads();
        if (c + 1 < nc) {
            const uint32_t so = (1 - s) * SM_STAGE;
            const __half* pa = a_p + (c + 1) * KC;
            const __half* pb = b_p + (c + 1) * KC;
#pragma unroll
            for (int q = 0; q < 4; q++) {
                cpa16(sA + so + q * 16, pa + q * 8);
                cpa16cg(sB + so + q * 16, pb + q * 8);
            }
            cpa_commit();
        }
        const uint32_t stA = lmA + s * SM_STAGE;
        const uint32_t stB = lmB + s * SM_STAGE;
#pragma unroll
        for (int ks = 0; ks < KC / 16; ks++) {
            uint32_t ah[2][4];
#pragma unroll
            for (int mi = 0; mi < 2; mi++)
                ldsm4(ah[mi], stA + mi * 16 * A_PITCH + ks * 32);
            uint32_t bb[4][4];
#pragma unroll
            for (int njp = 0; njp < 4; njp++)
                ldsm4(bb[njp], stB + njp * 16 * A_PITCH + ks * 32);
#pragma unroll
            for (int njp = 0; njp < 4; njp++)
#pragma unroll
                for (int sub = 0; sub < 2; sub++) {
                    int nj = njp * 2 + sub;
                    uint32_t b0 = bb[njp][sub];
                    uint32_t b1 = bb[njp][2 + sub];
#pragma unroll
                    for (int mi = 0; mi < 2; mi++)
                        mma16816(acc[mi][nj], ah[mi][0], ah[mi][1], ah[mi][2], ah[mi][3], b0, b1);
                }
        }
    }
}

// ---------------- vectorized transpose-convert (one 32x32 tile) ----------------
__device__ __forceinline__ void cvt4(const float* __restrict__ s, __half* __restrict__ oh,
                                     int K, int N, int remap_half, int bx, int by, int t,
                                     float tile[32][33]) {
    int c0 = bx * 32, k0 = by * 32;
    int k = t >> 3, c4 = (t & 7) << 2;
    float4 v = *(const float4*)&s[(size_t)(k0 + k) * N + c0 + c4];
    tile[k][c4]     = v.x;
    tile[k][c4 + 1] = v.y;
    tile[k][c4 + 2] = v.z;
    tile[k][c4 + 3] = v.w;
    __syncthreads();
    int nl = t >> 3, kq = (t & 7) << 2;
    int cc = c0 + nl;
    int n = remap_half ? (2 * (cc % remap_half) + cc / remap_half) : cc;
    __half2 h0 = __floats2half2_rn(tile[kq][nl], tile[kq + 1][nl]);
    __half2 h1 = __floats2half2_rn(tile[kq + 2][nl], tile[kq + 3][nl]);
    uint2 u;
    u.x = *(uint32_t*)&h0;
    u.y = *(uint32_t*)&h1;
    *(uint2*)&oh[(size_t)n * K + k0 + kq] = u;
}

// ---------------- merged prep: router + all weight conversions, one launch ----------------
__global__ __launch_bounds__(256) void k_prep(const float* __restrict__ x,
                                              const float* __restrict__ rw,
                                              float* __restrict__ out_logits,
                                              const float* __restrict__ gup,
                                              const float* __restrict__ dwn,
                                              const float* __restrict__ sgate,
                                              const float* __restrict__ sup,
                                              const float* __restrict__ sdown) {
    __shared__ float tile[32][33];
    int b = blockIdx.x, t = threadIdx.x;

    if (b < PREP_R) {
        // ---- router: 8 warps, 1 token each; fused x->fp16 ----
        int warp = t >> 5, lane = t & 31;
        int tok = b * 8 + warp;
        const float* xr = x + (size_t)tok * HDIM;
        __half* xo = g_x + (size_t)tok * HDIM;
        float acc[NE];
#pragma unroll
        for (int e = 0; e < NE; e++) acc[e] = 0.f;
        for (int i = lane; i < HDIM; i += 32) {
            float xv = xr[i];
            xo[i] = __float2half_rn(xv);
#pragma unroll
            for (int e = 0; e < NE; e++) acc[e] = fmaf(xv, rw[e * HDIM + i], acc[e]);
        }
#pragma unroll
        for (int e = 0; e < NE; e++) {
#pragma unroll
            for (int o = 16; o > 0; o >>= 1) acc[e] += __shfl_xor_sync(0xFFFFFFFFu, acc[e], o);
        }
        if (lane == 0) {
            if (out_logits) {
#pragma unroll
                for (int e = 0; e < NE; e++) out_logits[(size_t)tok * NE + e] = acc[e];
            }
            int e1 = 0; float v1 = acc[0];
#pragma unroll
            for (int e = 1; e < NE; e++) if (acc[e] > v1) { v1 = acc[e]; e1 = e; }
            int e2 = -1; float v2 = -1e30f;
#pragma unroll
            for (int e = 0; e < NE; e++) if (e != e1 && acc[e] > v2) { v2 = acc[e]; e2 = e; }
            g_tope[tok * 2 + 0] = e1; g_tops[tok * 2 + 0] = 1.f / (1.f + __expf(-v1));
            g_tope[tok * 2 + 1] = e2; g_tops[tok * 2 + 1] = 1.f / (1.f + __expf(-v2));
        }
    } else if (b < PREP_R + PREP_G) {
        int i = b - PREP_R;
        int bx = i & 127, by = (i >> 7) & 31, e = i >> 12;
        cvt4(gup + (size_t)e * HDIM * 2 * IDIM, g_wgu + (size_t)e * 2 * IDIM * HDIM,
             HDIM, 2 * IDIM, IDIM, bx, by, t, tile);
    } else if (b < PREP_R + PREP_G + PREP_D) {
        int i = b - PREP_R - PREP_G;
        int bx = i & 31, by = (i >> 5) & 63, e = i >> 11;
        cvt4(dwn + (size_t)e * IDIM * HDIM, g_wdn + (size_t)e * HDIM * IDIM,
             IDIM, HDIM, 0, bx, by, t, tile);
    } else {
        int i = b - PREP_R - PREP_G - PREP_D;
        size_t id = ((size_t)i * 256 + t) * 4;
        int j = (int)(id / HDIM), k = (int)(id % HDIM);
        float4 gv = *(const float4*)(sgate + id);
        float4 uv = *(const float4*)(sup + id);
        __half* dg = g_wsg + (size_t)(2 * j) * HDIM + k;
        __half* du = g_wsg + (size_t)(2 * j + 1) * HDIM + k;
        *(__half2*)(dg)     = __floats2half2_rn(gv.x, gv.y);
        *(__half2*)(dg + 2) = __floats2half2_rn(gv.z, gv.w);
        *(__half2*)(du)     = __floats2half2_rn(uv.x, uv.y);
        *(__half2*)(du + 2) = __floats2half2_rn(uv.z, uv.w);
        float4 v = *(const float4*)(sdown + id);
        *(__half2*)(g_wsd + id)     = __floats2half2_rn(v.x, v.y);
        *(__half2*)(g_wsd + id + 2) = __floats2half2_rn(v.z, v.w);
    }
}

// ---------------- single-CTA scatter: count + prefix + scatter ----------------
__global__ __launch_bounds__(1024) void k_scatter_all() {
    __shared__ int cnt[NE], off[NE], cur[NE];
    int tid = threadIdx.x;
    if (tid < NE) cnt[tid] = 0;
    __syncthreads();
    for (int p = tid; p < NPAIR; p += 1024)
        atomicAdd(&cnt[g_tope[p]], 1);
    __syncthreads();
    if (tid == 0) {
        int s = 0;
        for (int e = 0; e < NE; e++) { off[e] = s; s += cnt[e]; cur[e] = 0; }
    }
    __syncthreads();
    for (int p = tid; p < NPAIR; p += 1024) {
        int e = g_tope[p];
        int pos = atomicAdd(&cur[e], 1);
        int r = off[e] + pos;
        g_row_tok[r]  = p >> 1;
        g_row_sc[r]   = g_tops[p];
        g_row_slot[r] = p & 1;
    }
    if (tid < NE) { g_cnt[tid] = cnt[tid]; g_off[tid] = off[tid]; }
}

// ---------------- GEMM layer 1: routed gate_up (y<256) + shared gate_up (y>=256) ----------------
__global__ __launch_bounds__(256, 2) void tc_l1() {
    extern __shared__ char sm[];
    uint32_t sbu = smem_u32(sm);
    int t = threadIdx.x;
    int lane = t & 31, wid = t >> 5, g = lane >> 2, tg = lane & 3;
    int wm0 = (wid >> 1) * 32, wn0 = (wid & 1) * 64;
    int n0 = blockIdx.x * 128;
    int rb = t >> 1, half = t & 1;

    float acc[2][8][4];
#pragma unroll
    for (int a = 0; a < 2; a++)
#pragma unroll
        for (int b = 0; b < 8; b++)
#pragma unroll
            for (int q = 0; q < 4; q++) acc[a][b][q] = 0.f;

    int jb = n0 / 2 + wn0 / 2 + tg;

    if (blockIdx.y < 256) {
        // ---- routed gate_up ----
        int e = blockIdx.y >> 5, rt = blockIdx.y & 31;
        int cnt = g_cnt[e];
        int row0 = rt * 128;
        if (row0 >= cnt) return;
        int base = g_off[e];
        int rr = base + min(row0 + rb, cnt - 1);
        const __half* ap = g_x + (size_t)g_row_tok[rr] * HDIM + half * 32;
        const __half* bp = g_wgu + (size_t)e * 2 * IDIM * HDIM + (size_t)(n0 + rb) * HDIM + half * 32;

        gemm_core(ap, bp, HDIM, sm, sbu, acc);

#pragma unroll
        for (int mi = 0; mi < 2; mi++)
#pragma unroll
            for (int dq = 0; dq < 2; dq++) {
                int rl = wm0 + mi * 16 + g + dq * 8;
                if (row0 + rl < cnt) {
                    int grow = base + row0 + rl;
                    float sc = g_row_sc[grow];
                    __half* dh = g_act + (size_t)grow * IDIM;
#pragma unroll
                    for (int nj = 0; nj < 8; nj++) {
                        float v = silu_mul(sc * acc[mi][nj][dq * 2], sc * acc[mi][nj][dq * 2 + 1]);
                        dh[jb + nj * 4] = __float2half_rn(v);
                    }
                }
            }
    } else {
        // ---- shared gate_up ----
        int row0 = (blockIdx.y - 256) * 128;
        const __half* ap = g_x + (size_t)(row0 + rb) * HDIM + half * 32;
        const __half* bp = g_wsg + (size_t)(n0 + rb) * HDIM + half * 32;

        gemm_core(ap, bp, HDIM, sm, sbu, acc);

#pragma unroll
        for (int mi = 0; mi < 2; mi++)
#pragma unroll
            for (int dq = 0; dq < 2; dq++) {
                int rl = wm0 + mi * 16 + g + dq * 8;
                __half* dh = g_acts + (size_t)(row0 + rl) * IDIM;
#pragma unroll
                for (int nj = 0; nj < 8; nj++) {
                    float v = silu_mul(acc[mi][nj][dq * 2], acc[mi][nj][dq * 2 + 1]);
                    dh[jb + nj * 4] = __float2half_rn(v);
                }
            }
    }
}

// ---------------- GEMM layer 2: routed down ----------------
__global__ __launch_bounds__(256, 2) void tc_dn_routed() {
    int e = blockIdx.y >> 5, rt = blockIdx.y & 31;
    int cnt = g_cnt[e];
    int row0 = rt * 128;
    if (row0 >= cnt) return;
    int base = g_off[e];

    extern __shared__ char sm[];
    uint32_t sbu = smem_u32(sm);
    int t = threadIdx.x, rb = t >> 1, half = t & 1;
    const __half* ap = g_act + (size_t)(base + min(row0 + rb, cnt - 1)) * IDIM + half * 32;
    int n0 = blockIdx.x * 128;
    const __half* bp = g_wdn + (size_t)e * HDIM * IDIM + (size_t)(n0 + rb) * IDIM + half * 32;

    float acc[2][8][4];
#pragma unroll
    for (int a = 0; a < 2; a++)
#pragma unroll
        for (int b = 0; b < 8; b++)
#pragma unroll
            for (int q = 0; q < 4; q++) acc[a][b][q] = 0.f;

    gemm_core(ap, bp, IDIM, sm, sbu, acc);

    int lane = t & 31, wid = t >> 5, g = lane >> 2, tg = lane & 3;
    int wm0 = (wid >> 1) * 32, wn0 = (wid & 1) * 64;
    int colb = n0 + wn0 + tg * 2;
#pragma unroll
    for (int mi = 0; mi < 2; mi++)
#pragma unroll
        for (int dq = 0; dq < 2; dq++) {
            int rl = wm0 + mi * 16 + g + dq * 8;
            if (row0 + rl < cnt) {
                int grow = base + row0 + rl;
                int tok = g_row_tok[grow], slot = g_row_slot[grow];
                float* dst = g_partial[slot] + (size_t)tok * HDIM;
#pragma unroll
                for (int nj = 0; nj < 8; nj++) {
                    float2 v = {acc[mi][nj][dq * 2], acc[mi][nj][dq * 2 + 1]};
                    *(float2*)&dst[colb + nj * 8] = v;
                }
            }
        }
}

// ---------------- GEMM layer 3: shared down + final add ----------------
__global__ __launch_bounds__(256, 2) void tc_dn_shared(float* __restrict__ out) {
    int row0 = blockIdx.y * 128;
    int n0 = blockIdx.x * 128;

    extern __shared__ char sm[];
    uint32_t sbu = smem_u32(sm);
    int t = threadIdx.x, rb = t >> 1, half = t & 1;
    const __half* ap = g_acts + (size_t)(row0 + rb) * IDIM + half * 32;
    const __half* bp = g_wsd + (size_t)(n0 + rb) * IDIM + half * 32;

    float acc[2][8][4];
#pragma unroll
    for (int a = 0; a < 2; a++)
#pragma unroll
        for (int b = 0; b < 8; b++)
#pragma unroll
            for (int q = 0; q < 4; q++) acc[a][b][q] = 0.f;

    gemm_core(ap, bp, IDIM, sm, sbu, acc);

    int lane = t & 31, wid = t >> 5, g = lane >> 2, tg = lane & 3;
    int wm0 = (wid >> 1) * 32, wn0 = (wid & 1) * 64;
    int colb = n0 + wn0 + tg * 2;
#pragma unroll
    for (int mi = 0; mi < 2; mi++)
#pragma unroll
        for (int dq = 0; dq < 2; dq++) {
            int row = row0 + wm0 + mi * 16 + g + dq * 8;
            size_t rbase = (size_t)row * HDIM;
#pragma unroll
            for (int nj = 0; nj < 8; nj++) {
                size_t idx = rbase + colb + nj * 8;
                float2 p0 = *(const float2*)&g_partial[0][idx];
                float2 p1 = *(const float2*)&g_partial[1][idx];
                float2 v;
                v.x = acc[mi][nj][dq * 2] + p0.x + p1.x;
                v.y = acc[mi][nj][dq * 2 + 1] + p0.y + p1.y;
                *(float2*)&out[idx] = v;
            }
        }
}

// ---------------- launch ----------------
extern "C" void kernel_launch(void* const* d_in, const int* in_sizes, int n_in,
                              void* d_out, int out_size) {
    const float* x     = (const float*)d_in[0];   // [T, H]
    const float* rw    = (const float*)d_in[1];   // [E, H]
    const float* gup   = (const float*)d_in[2];   // [E, H, 2I]
    const float* dwn   = (const float*)d_in[3];   // [E, I, H]
    const float* sgate = (const float*)d_in[4];   // [I, H]
    const float* sup   = (const float*)d_in[5];   // [I, H]
    const float* sdown = (const float*)d_in[6];   // [H, I]
    float* out = (float*)d_out;

    float* out_logits = nullptr;
    if (out_size >= TTOK * HDIM + TTOK * NE) out_logits = out + (size_t)TTOK * HDIM;

    cudaFuncSetAttribute(tc_l1,        cudaFuncAttributeMaxDynamicSharedMemorySize, SMEM_GEMM);
    cudaFuncSetAttribute(tc_dn_routed, cudaFuncAttributeMaxDynamicSharedMemorySize, SMEM_GEMM);
    cudaFuncSetAttribute(tc_dn_shared, cudaFuncAttributeMaxDynamicSharedMemorySize, SMEM_GEMM);

    k_prep<<<PREP_TOTAL, 256>>>(x, rw, out_logits, gup, dwn, sgate, sup, sdown);
    k_scatter_all<<<1, 1024>>>();

    tc_l1<<<dim3(2 * IDIM / 128, 256 + TTOK / 128), 256, SMEM_GEMM>>>();
    tc_dn_routed<<<dim3(HDIM / 128, NE * 32), 256, SMEM_GEMM>>>();
    tc_dn_shared<<<dim3(HDIM / 128, TTOK / 128), 256, SMEM_GEMM>>>(out);
}

// round 16
// speedup vs baseline: 1.3476x; 1.0255x over previous
#include <cuda_runtime.h>
#include <cuda_fp16.h>
#include <stdint.h>
#include <math.h>

// Problem constants
#define TTOK 4096
#define HDIM 1024
#define IDIM 2048
#define NE   8
#define NPAIR (TTOK * 2)

// GEMM config: 128x128 CTA tile, 8 warps (4M x 2N of 32x64), KC=64, double-buffered
#define KC 64
#define A_PITCH 144              // bytes per smem row (64 fp16 + pad; ldmatrix conflict-free)
#define SM_A 0
#define SM_B (128 * A_PITCH)                 // 18432
#define SM_STAGE (2 * 128 * A_PITCH)         // 36864
#define SMEM_GEMM (2 * SM_STAGE)             // 73728 -> 2 CTAs/SM
#define EP_PITCH 72                          // epilogue staging pitch (halfs) = 144 B

// prep-kernel job ranges
#define PREP_R 512                            // router: 8 tokens/block
#define PREP_G 32768                          // gup transpose: 128 x 32 x 8
#define PREP_D 16384                          // dwn transpose: 32 x 64 x 8
#define PREP_S 2048                           // shared cvt: (I*H)/1024
#define PREP_TOTAL (PREP_R + PREP_G + PREP_D + PREP_S)

// ---------------- scratch (static __device__ — no allocation) ----------------
__device__ __half g_x[(size_t)TTOK * HDIM];             // x fp16 (written by router)
__device__ __half g_act[(size_t)NPAIR * IDIM];          // routed swiglu act fp16
__device__ __half g_acts[(size_t)TTOK * IDIM];          // shared swiglu act fp16
__device__ float g_partial[2][(size_t)TTOK * HDIM];     // per-slot routed outputs
__device__ int   g_row_tok[NPAIR];
__device__ float g_row_sc[NPAIR];
__device__ int   g_row_slot[NPAIR];
__device__ int   g_tope[NPAIR];
__device__ float g_tops[NPAIR];
__device__ int   g_cnt[NE];
__device__ int   g_off[NE];

// fp16 weights, [n][k] col-major-for-mma layouts
__device__ __half g_wgu[(size_t)NE * 2 * IDIM * HDIM];   // interleaved gate/up rows
__device__ __half g_wdn[(size_t)NE * HDIM * IDIM];       // [H][I]
__device__ __half g_wsg[(size_t)2 * IDIM * HDIM];        // shared gate/up interleaved
__device__ __half g_wsd[(size_t)HDIM * IDIM];            // [H][I]

// ---------------- small helpers ----------------
__device__ __forceinline__ uint32_t smem_u32(const void* p) {
    uint32_t a;
    asm("{ .reg .u64 t; cvta.to.shared.u64 t, %1; cvt.u32.u64 %0, t; }" : "=r"(a) : "l"(p));
    return a;
}
__device__ __forceinline__ void cpa16(uint32_t saddr, const void* g) {
    asm volatile("cp.async.ca.shared.global [%0], [%1], 16;" :: "r"(saddr), "l"(g));
}
__device__ __forceinline__ void cpa_commit() {
    asm volatile("cp.async.commit_group;" ::: "memory");
}
__device__ __forceinline__ void cpa_wait0() {
    asm volatile("cp.async.wait_group 0;" ::: "memory");
}
__device__ __forceinline__ float silu_mul(float g, float u) {
    return u * g / (1.f + __expf(-g));
}
__device__ __forceinline__ void mma16816(float d[4], uint32_t a0, uint32_t a1, uint32_t a2,
                                         uint32_t a3, uint32_t b0, uint32_t b1) {
    asm volatile(
        "mma.sync.aligned.m16n8k16.row.col.f32.f16.f16.f32 "
        "{%0,%1,%2,%3}, {%4,%5,%6,%7}, {%8,%9}, {%0,%1,%2,%3};"
        : "+f"(d[0]), "+f"(d[1]), "+f"(d[2]), "+f"(d[3])
        : "r"(a0), "r"(a1), "r"(a2), "r"(a3), "r"(b0), "r"(b1));
}
__device__ __forceinline__ void ldsm4(uint32_t r[4], uint32_t addr) {
    asm volatile("ldmatrix.sync.aligned.m8n8.x4.shared.b16 {%0,%1,%2,%3}, [%4];"
                 : "=r"(r[0]), "=r"(r[1]), "=r"(r[2]), "=r"(r[3]) : "r"(addr));
}

// ---------------- GEMM core: C[128x128] += A * B  (fp16 x fp16, f32 accum) ----------------
// 8 warps (4M x 2N), 32x64 warp tiles, ldmatrix frags, 2-stage cp.async pipeline.
__device__ __forceinline__ void gemm_core(const __half* __restrict__ a_p,
                                          const __half* __restrict__ b_p,
                                          int Ktot, char* sm, uint32_t sbu,
                                          float acc[2][8][4]) {
    const int t = threadIdx.x;
    const int lane = t & 31, wid = t >> 5;
    const int wm0 = (wid >> 1) * 32, wn0 = (wid & 1) * 64;
    const int nc = Ktot / KC;
    const int lrow = lane & 15, lhalf = lane >> 4;   // ldmatrix lane mapping

    const uint32_t sA = sbu + SM_A + (t >> 1) * A_PITCH + (t & 1) * 64;
    const uint32_t sB = sbu + SM_B + (t >> 1) * A_PITCH + (t & 1) * 64;
    const uint32_t lmA = sbu + SM_A + (wm0 + lrow) * A_PITCH + lhalf * 16;
    const uint32_t lmB = sbu + SM_B + (wn0 + lrow) * A_PITCH + lhalf * 16;

    // prologue: chunk 0 into stage 0
#pragma unroll
    for (int q = 0; q < 4; q++) {
        cpa16(sA + q * 16, a_p + q * 8);
        cpa16(sB + q * 16, b_p + q * 8);
    }
    cpa_commit();

    for (int c = 0; c < nc; c++) {
        const int s = c & 1;
        cpa_wait0();
        __syncthreads();
        if (c + 1 < nc) {
            const uint32_t so = (1 - s) * SM_STAGE;
            const __half* pa = a_p + (c + 1) * KC;
            const __half* pb = b_p + (c + 1) * KC;
#pragma unroll
            for (int q = 0; q < 4; q++) {
                cpa16(sA + so + q * 16, pa + q * 8);
                cpa16(sB + so + q * 16, pb + q * 8);
            }
            cpa_commit();
        }
        const uint32_t stA = lmA + s * SM_STAGE;
        const uint32_t stB = lmB + s * SM_STAGE;
#pragma unroll
        for (int ks = 0; ks < KC / 16; ks++) {
            uint32_t ah[2][4];
#pragma unroll
            for (int mi = 0; mi < 2; mi++)
                ldsm4(ah[mi], stA + mi * 16 * A_PITCH + ks * 32);
            uint32_t bb[4][4];
#pragma unroll
            for (int njp = 0; njp < 4; njp++)
                ldsm4(bb[njp], stB + njp * 16 * A_PITCH + ks * 32);
#pragma unroll
            for (int njp = 0; njp < 4; njp++)
#pragma unroll
                for (int sub = 0; sub < 2; sub++) {
                    int nj = njp * 2 + sub;
                    uint32_t b0 = bb[njp][sub];
                    uint32_t b1 = bb[njp][2 + sub];
#pragma unroll
                    for (int mi = 0; mi < 2; mi++)
                        mma16816(acc[mi][nj], ah[mi][0], ah[mi][1], ah[mi][2], ah[mi][3], b0, b1);
                }
        }
    }
}

// ---------------- vectorized transpose-convert (one 32x32 tile) ----------------
__device__ __forceinline__ void cvt4(const float* __restrict__ s, __half* __restrict__ oh,
                                     int K, int N, int remap_half, int bx, int by, int t,
                                     float tile[32][33]) {
    int c0 = bx * 32, k0 = by * 32;
    int k = t >> 3, c4 = (t & 7) << 2;
    float4 v = *(const float4*)&s[(size_t)(k0 + k) * N + c0 + c4];
    tile[k][c4]     = v.x;
    tile[k][c4 + 1] = v.y;
    tile[k][c4 + 2] = v.z;
    tile[k][c4 + 3] = v.w;
    __syncthreads();
    int nl = t >> 3, kq = (t & 7) << 2;
    int cc = c0 + nl;
    int n = remap_half ? (2 * (cc % remap_half) + cc / remap_half) : cc;
    __half2 h0 = __floats2half2_rn(tile[kq][nl], tile[kq + 1][nl]);
    __half2 h1 = __floats2half2_rn(tile[kq + 2][nl], tile[kq + 3][nl]);
    uint2 u;
    u.x = *(uint32_t*)&h0;
    u.y = *(uint32_t*)&h1;
    *(uint2*)&oh[(size_t)n * K + k0 + kq] = u;
}

// ---------------- merged prep: router + all weight conversions, one launch ----------------
__global__ __launch_bounds__(256) void k_prep(const float* __restrict__ x,
                                              const float* __restrict__ rw,
                                              float* __restrict__ out_logits,
                                              const float* __restrict__ gup,
                                              const float* __restrict__ dwn,
                                              const float* __restrict__ sgate,
                                              const float* __restrict__ sup,
                                              const float* __restrict__ sdown) {
    __shared__ float tile[32][33];
    int b = blockIdx.x, t = threadIdx.x;

    if (b < PREP_R) {
        // ---- router: 8 warps, 1 token each; fused x->fp16 ----
        int warp = t >> 5, lane = t & 31;
        int tok = b * 8 + warp;
        const float* xr = x + (size_t)tok * HDIM;
        __half* xo = g_x + (size_t)tok * HDIM;
        float acc[NE];
#pragma unroll
        for (int e = 0; e < NE; e++) acc[e] = 0.f;
        for (int i = lane; i < HDIM; i += 32) {
            float xv = xr[i];
            xo[i] = __float2half_rn(xv);
#pragma unroll
            for (int e = 0; e < NE; e++) acc[e] = fmaf(xv, rw[e * HDIM + i], acc[e]);
        }
#pragma unroll
        for (int e = 0; e < NE; e++) {
#pragma unroll
            for (int o = 16; o > 0; o >>= 1) acc[e] += __shfl_xor_sync(0xFFFFFFFFu, acc[e], o);
        }
        if (lane == 0) {
            if (out_logits) {
#pragma unroll
                for (int e = 0; e < NE; e++) out_logits[(size_t)tok * NE + e] = acc[e];
            }
            int e1 = 0; float v1 = acc[0];
#pragma unroll
            for (int e = 1; e < NE; e++) if (acc[e] > v1) { v1 = acc[e]; e1 = e; }
            int e2 = -1; float v2 = -1e30f;
#pragma unroll
            for (int e = 0; e < NE; e++) if (e != e1 && acc[e] > v2) { v2 = acc[e]; e2 = e; }
            g_tope[tok * 2 + 0] = e1; g_tops[tok * 2 + 0] = 1.f / (1.f + __expf(-v1));
            g_tope[tok * 2 + 1] = e2; g_tops[tok * 2 + 1] = 1.f / (1.f + __expf(-v2));
        }
    } else if (b < PREP_R + PREP_G) {
        int i = b - PREP_R;
        int bx = i & 127, by = (i >> 7) & 31, e = i >> 12;
        cvt4(gup + (size_t)e * HDIM * 2 * IDIM, g_wgu + (size_t)e * 2 * IDIM * HDIM,
             HDIM, 2 * IDIM, IDIM, bx, by, t, tile);
    } else if (b < PREP_R + PREP_G + PREP_D) {
        int i = b - PREP_R - PREP_G;
        int bx = i & 31, by = (i >> 5) & 63, e = i >> 11;
        cvt4(dwn + (size_t)e * IDIM * HDIM, g_wdn + (size_t)e * HDIM * IDIM,
             IDIM, HDIM, 0, bx, by, t, tile);
    } else {
        int i = b - PREP_R - PREP_G - PREP_D;
        size_t id = ((size_t)i * 256 + t) * 4;
        int j = (int)(id / HDIM), k = (int)(id % HDIM);
        float4 gv = *(const float4*)(sgate + id);
        float4 uv = *(const float4*)(sup + id);
        __half* dg = g_wsg + (size_t)(2 * j) * HDIM + k;
        __half* du = g_wsg + (size_t)(2 * j + 1) * HDIM + k;
        *(__half2*)(dg)     = __floats2half2_rn(gv.x, gv.y);
        *(__half2*)(dg + 2) = __floats2half2_rn(gv.z, gv.w);
        *(__half2*)(du)     = __floats2half2_rn(uv.x, uv.y);
        *(__half2*)(du + 2) = __floats2half2_rn(uv.z, uv.w);
        float4 v = *(const float4*)(sdown + id);
        *(__half2*)(g_wsd + id)     = __floats2half2_rn(v.x, v.y);
        *(__half2*)(g_wsd + id + 2) = __floats2half2_rn(v.z, v.w);
    }
}

// ---------------- single-CTA scatter: count + prefix + scatter ----------------
__global__ __launch_bounds__(1024) void k_scatter_all() {
    __shared__ int cnt[NE], off[NE], cur[NE];
    int tid = threadIdx.x;
    if (tid < NE) cnt[tid] = 0;
    __syncthreads();
    for (int p = tid; p < NPAIR; p += 1024)
        atomicAdd(&cnt[g_tope[p]], 1);
    __syncthreads();
    if (tid == 0) {
        int s = 0;
        for (int e = 0; e < NE; e++) { off[e] = s; s += cnt[e]; cur[e] = 0; }
    }
    __syncthreads();
    for (int p = tid; p < NPAIR; p += 1024) {
        int e = g_tope[p];
        int pos = atomicAdd(&cur[e], 1);
        int r = off[e] + pos;
        g_row_tok[r]  = p >> 1;
        g_row_sc[r]   = g_tops[p];
        g_row_slot[r] = p & 1;
    }
    if (tid < NE) { g_cnt[tid] = cnt[tid]; g_off[tid] = off[tid]; }
}

// ---------------- GEMM layer 1: routed gate_up (y<256) + shared gate_up (y>=256) ----------------
// Epilogue staged through smem for coalesced 128B activation writes.
__global__ __launch_bounds__(256, 2) void tc_l1() {
    extern __shared__ char sm[];
    uint32_t sbu = smem_u32(sm);
    int t = threadIdx.x;
    int lane = t & 31, wid = t >> 5, g = lane >> 2, tg = lane & 3;
    int wm0 = (wid >> 1) * 32, wn0 = (wid & 1) * 64;
    int n0 = blockIdx.x * 128;
    int rb = t >> 1, half = t & 1;

    float acc[2][8][4];
#pragma unroll
    for (int a = 0; a < 2; a++)
#pragma unroll
        for (int b = 0; b < 8; b++)
#pragma unroll
            for (int q = 0; q < 4; q++) acc[a][b][q] = 0.f;

    int jcb = wn0 / 2 + tg;                      // CTA-local epilogue column base
    __half* ep = (__half*)sm;                    // [128][EP_PITCH] staging (18KB)

    if (blockIdx.y < 256) {
        // ---- routed gate_up ----
        int e = blockIdx.y >> 5, rt = blockIdx.y & 31;
        int cnt = g_cnt[e];
        int row0 = rt * 128;
        if (row0 >= cnt) return;
        int base = g_off[e];
        int rr = base + min(row0 + rb, cnt - 1);
        const __half* ap = g_x + (size_t)g_row_tok[rr] * HDIM + half * 32;
        const __half* bp = g_wgu + (size_t)e * 2 * IDIM * HDIM + (size_t)(n0 + rb) * HDIM + half * 32;

        gemm_core(ap, bp, HDIM, sm, sbu, acc);
        __syncthreads();   // mainloop readers done before staging overwrites smem

#pragma unroll
        for (int mi = 0; mi < 2; mi++)
#pragma unroll
            for (int dq = 0; dq < 2; dq++) {
                int rl = wm0 + mi * 16 + g + dq * 8;
                if (row0 + rl < cnt) {
                    float sc = g_row_sc[base + row0 + rl];
#pragma unroll
                    for (int nj = 0; nj < 8; nj++) {
                        float v = silu_mul(sc * acc[mi][nj][dq * 2], sc * acc[mi][nj][dq * 2 + 1]);
                        ep[rl * EP_PITCH + jcb + nj * 4] = __float2half_rn(v);
                    }
                }
            }
        __syncthreads();
        // coalesced writeback: 2 threads per row, 64B each
        {
            int r = t >> 1, cseg = (t & 1) * 32;
            if (row0 + r < cnt) {
                int grow = base + row0 + r;
                const uint4* src = (const uint4*)(ep + r * EP_PITCH + cseg);
                uint4* dst = (uint4*)(g_act + (size_t)grow * IDIM + n0 / 2 + cseg);
#pragma unroll
                for (int q = 0; q < 4; q++) dst[q] = src[q];
            }
        }
    } else {
        // ---- shared gate_up ----
        int row0 = (blockIdx.y - 256) * 128;
        const __half* ap = g_x + (size_t)(row0 + rb) * HDIM + half * 32;
        const __half* bp = g_wsg + (size_t)(n0 + rb) * HDIM + half * 32;

        gemm_core(ap, bp, HDIM, sm, sbu, acc);
        __syncthreads();

#pragma unroll
        for (int mi = 0; mi < 2; mi++)
#pragma unroll
            for (int dq = 0; dq < 2; dq++) {
                int rl = wm0 + mi * 16 + g + dq * 8;
#pragma unroll
                for (int nj = 0; nj < 8; nj++) {
                    float v = silu_mul(acc[mi][nj][dq * 2], acc[mi][nj][dq * 2 + 1]);
                    ep[rl * EP_PITCH + jcb + nj * 4] = __float2half_rn(v);
                }
            }
        __syncthreads();
        {
            int r = t >> 1, cseg = (t & 1) * 32;
            const uint4* src = (const uint4*)(ep + r * EP_PITCH + cseg);
            uint4* dst = (uint4*)(g_acts + (size_t)(row0 + r) * IDIM + n0 / 2 + cseg);
#pragma unroll
            for (int q = 0; q < 4; q++) dst[q] = src[q];
        }
    }
}

// ---------------- GEMM layer 2: routed down ----------------
__global__ __launch_bounds__(256, 2) void tc_dn_routed() {
    int e = blockIdx.y >> 5, rt = blockIdx.y & 31;
    int cnt = g_cnt[e];
    int row0 = rt * 128;
    if (row0 >= cnt) return;
    int base = g_off[e];

    extern __shared__ char sm[];
    uint32_t sbu = smem_u32(sm);
    int t = threadIdx.x, rb = t >> 1, half = t & 1;
    const __half* ap = g_act + (size_t)(base + min(row0 + rb, cnt - 1)) * IDIM + half * 32;
    int n0 = blockIdx.x * 128;
    const __half* bp = g_wdn + (size_t)e * HDIM * IDIM + (size_t)(n0 + rb) * IDIM + half * 32;

    float acc[2][8][4];
#pragma unroll
    for (int a = 0; a < 2; a++)
#pragma unroll
        for (int b = 0; b < 8; b++)
#pragma unroll
            for (int q = 0; q < 4; q++) acc[a][b][q] = 0.f;

    gemm_core(ap, bp, IDIM, sm, sbu, acc);

    int lane = t & 31, wid = t >> 5, g = lane >> 2, tg = lane & 3;
    int wm0 = (wid >> 1) * 32, wn0 = (wid & 1) * 64;
    int colb = n0 + wn0 + tg * 2;
#pragma unroll
    for (int mi = 0; mi < 2; mi++)
#pragma unroll
        for (int dq = 0; dq < 2; dq++) {
            int rl = wm0 + mi * 16 + g + dq * 8;
            if (row0 + rl < cnt) {
                int grow = base + row0 + rl;
                int tok = g_row_tok[grow], slot = g_row_slot[grow];
                float* dst = g_partial[slot] + (size_t)tok * HDIM;
#pragma unroll
                for (int nj = 0; nj < 8; nj++) {
                    float2 v = {acc[mi][nj][dq * 2], acc[mi][nj][dq * 2 + 1]};
                    *(float2*)&dst[colb + nj * 8] = v;
                }
            }
        }
}

// ---------------- GEMM layer 3: shared down + final add ----------------
__global__ __launch_bounds__(256, 2) void tc_dn_shared(float* __restrict__ out) {
    int row0 = blockIdx.y * 128;
    int n0 = blockIdx.x * 128;

    extern __shared__ char sm[];
    uint32_t sbu = smem_u32(sm);
    int t = threadIdx.x, rb = t >> 1, half = t & 1;
    const __half* ap = g_acts + (size_t)(row0 + rb) * IDIM + half * 32;
    const __half* bp = g_wsd + (size_t)(n0 + rb) * IDIM + half * 32;

    float acc[2][8][4];
#pragma unroll
    for (int a = 0; a < 2; a++)
#pragma unroll
        for (int b = 0; b < 8; b++)
#pragma unroll
            for (int q = 0; q < 4; q++) acc[a][b][q] = 0.f;

    gemm_core(ap, bp, IDIM, sm, sbu, acc);

    int lane = t & 31, wid = t >> 5, g = lane >> 2, tg = lane & 3;
    int wm0 = (wid >> 1) * 32, wn0 = (wid & 1) * 64;
    int colb = n0 + wn0 + tg * 2;
#pragma unroll
    for (int mi = 0; mi < 2; mi++)
#pragma unroll
        for (int dq = 0; dq < 2; dq++) {
            int row = row0 + wm0 + mi * 16 + g + dq * 8;
            size_t rbase = (size_t)row * HDIM;
#pragma unroll
            for (int nj = 0; nj < 8; nj++) {
                size_t idx = rbase + colb + nj * 8;
                float2 p0 = *(const float2*)&g_partial[0][idx];
                float2 p1 = *(const float2*)&g_partial[1][idx];
                float2 v;
                v.x = acc[mi][nj][dq * 2] + p0.x + p1.x;
                v.y = acc[mi][nj][dq * 2 + 1] + p0.y + p1.y;
                *(float2*)&out[idx] = v;
            }
        }
}

// ---------------- launch ----------------
extern "C" void kernel_launch(void* const* d_in, const int* in_sizes, int n_in,
                              void* d_out, int out_size) {
    const float* x     = (const float*)d_in[0];   // [T, H]
    const float* rw    = (const float*)d_in[1];   // [E, H]
    const float* gup   = (const float*)d_in[2];   // [E, H, 2I]
    const float* dwn   = (const float*)d_in[3];   // [E, I, H]
    const float* sgate = (const float*)d_in[4];   // [I, H]
    const float* sup   = (const float*)d_in[5];   // [I, H]
    const float* sdown = (const float*)d_in[6];   // [H, I]
    float* out = (float*)d_out;

    float* out_logits = nullptr;
    if (out_size >= TTOK * HDIM + TTOK * NE) out_logits = out + (size_t)TTOK * HDIM;

    cudaFuncSetAttribute(tc_l1,        cudaFuncAttributeMaxDynamicSharedMemorySize, SMEM_GEMM);
    cudaFuncSetAttribute(tc_dn_routed, cudaFuncAttributeMaxDynamicSharedMemorySize, SMEM_GEMM);
    cudaFuncSetAttribute(tc_dn_shared, cudaFuncAttributeMaxDynamicSharedMemorySize, SMEM_GEMM);

    k_prep<<<PREP_TOTAL, 256>>>(x, rw, out_logits, gup, dwn, sgate, sup, sdown);
    k_scatter_all<<<1, 1024>>>();

    tc_l1<<<dim3(2 * IDIM / 128, 256 + TTOK / 128), 256, SMEM_GEMM>>>();
    tc_dn_routed<<<dim3(HDIM / 128, NE * 32), 256, SMEM_GEMM>>>();
    tc_dn_shared<<<dim3(HDIM / 128, TTOK / 128), 256, SMEM_GEMM>>>(out);
}

// round 17
// speedup vs baseline: 1.4791x; 1.0976x over previous
#include <cuda_runtime.h>
#include <cuda_fp16.h>
#include <stdint.h>
#include <math.h>

// Problem constants
#define TTOK 4096
#define HDIM 1024
#define IDIM 2048
#define NE   8
#define NPAIR (TTOK * 2)

// GEMM config: 128x128 CTA tile, 8 warps (4M x 2N of 32x64), KC=64, double-buffered
// A tile: 144B-pitch padded rows (cp.async per-thread). B tile: 128B-pitch swizzled,
// contiguous 16KB blocks in gmem, loaded with ONE cp.async.bulk per chunk.
#define KC 64
#define A_PITCH 144
#define A_BYTES (128 * A_PITCH)              // 18432
#define B_BYTES 16384
#define SM_A 0
#define SM_B A_BYTES
#define STG (A_BYTES + B_BYTES)              // 34816
#define OFF_MB (2 * STG)                     // 2 mbarriers at +0, +8
#define SMEM_GEMM (2 * STG + 64)             // 69696 -> 2 CTAs/SM
#define EP_PITCH 72                          // tc_l1 epilogue staging pitch (halfs)

// prep-kernel job ranges
#define PREP_R 512
#define PREP_G 32768
#define PREP_D 16384
#define PREP_S 2048
#define PREP_TOTAL (PREP_R + PREP_G + PREP_D + PREP_S)

// ---------------- scratch (static __device__ — no allocation) ----------------
__device__ __half g_x[(size_t)TTOK * HDIM];
__device__ __half g_act[(size_t)NPAIR * IDIM];
__device__ __half g_acts[(size_t)TTOK * IDIM];
__device__ float g_partial[2][(size_t)TTOK * HDIM];
__device__ int   g_row_tok[NPAIR];
__device__ float g_row_sc[NPAIR];
__device__ int   g_row_slot[NPAIR];
__device__ int   g_tope[NPAIR];
__device__ float g_tops[NPAIR];
__device__ int   g_cnt[NE];
__device__ int   g_off[NE];

// fp16 weights, tile-blocked swizzled layouts: [ntile][kchunk][128 rows][128B swizzled]
__device__ __align__(128) __half g_wgu[(size_t)NE * 2 * IDIM * HDIM];
__device__ __align__(128) __half g_wdn[(size_t)NE * HDIM * IDIM];
__device__ __align__(128) __half g_wsg[(size_t)2 * IDIM * HDIM];
__device__ __align__(128) __half g_wsd[(size_t)HDIM * IDIM];

// ---------------- small helpers ----------------
__device__ __forceinline__ uint32_t smem_u32(const void* p) {
    uint32_t a;
    asm("{ .reg .u64 t; cvta.to.shared.u64 t, %1; cvt.u32.u64 %0, t; }" : "=r"(a) : "l"(p));
    return a;
}
__device__ __forceinline__ void cpa16(uint32_t saddr, const void* g) {
    asm volatile("cp.async.ca.shared.global [%0], [%1], 16;" :: "r"(saddr), "l"(g));
}
__device__ __forceinline__ void cpa_commit() {
    asm volatile("cp.async.commit_group;" ::: "memory");
}
__device__ __forceinline__ void cpa_wait0() {
    asm volatile("cp.async.wait_group 0;" ::: "memory");
}
__device__ __forceinline__ void bulkcp(uint32_t sdst, const void* gsrc, uint32_t bytes,
                                       uint32_t mbar) {
    asm volatile(
        "cp.async.bulk.shared::cta.global.mbarrier::complete_tx::bytes [%0], [%1], %2, [%3];"
        :: "r"(sdst), "l"(gsrc), "r"(bytes), "r"(mbar) : "memory");
}
#define MBARRIER_INIT(addr, cnt) \
    asm volatile("mbarrier.init.shared.b64 [%0], %1;" :: "r"((uint32_t)(addr)), "r"((uint32_t)(cnt)) : "memory")
__device__ __forceinline__ void mb_expect(uint32_t mbar, uint32_t bytes) {
    asm volatile("mbarrier.arrive.expect_tx.shared.b64 _, [%0], %1;"
                 :: "r"(mbar), "r"(bytes) : "memory");
}
#define MBARRIER_WAIT_PARITY(mbar_smem_addr, phase_parity) do { \
    uint32_t _mbar = (uint32_t)(mbar_smem_addr); \
    uint32_t _parity = (uint32_t)(phase_parity); \
    uint32_t _done; \
    asm volatile("{\n\t.reg .pred p;\n\t" \
        "mbarrier.try_wait.parity.acquire.cta.shared::cta.b64 p, [%1], %2;\n\t" \
        "selp.b32 %0, 1, 0, p;\n\t}" \
        : "=r"(_done) : "r"(_mbar), "r"(_parity) : "memory"); \
    if (!_done) { \
        asm volatile("{\n\t.reg .pred P1;\n\t" \
            "WAIT_LOOP_%=:\n\t" \
            "mbarrier.try_wait.parity.acquire.cta.shared::cta.b64 P1, [%0], %1, 0x989680;\n\t" \
            "@P1 bra.uni WAIT_DONE_%=;\n\t" \
            "bra.uni WAIT_LOOP_%=;\n\t" \
            "WAIT_DONE_%=:\n\t}" \
            :: "r"(_mbar), "r"(_parity) : "memory"); \
    } \
} while (0)

__device__ __forceinline__ float silu_mul(float g, float u) {
    return u * g / (1.f + __expf(-g));
}
__device__ __forceinline__ void mma16816(float d[4], uint32_t a0, uint32_t a1, uint32_t a2,
                                         uint32_t a3, uint32_t b0, uint32_t b1) {
    asm volatile(
        "mma.sync.aligned.m16n8k16.row.col.f32.f16.f16.f32 "
        "{%0,%1,%2,%3}, {%4,%5,%6,%7}, {%8,%9}, {%0,%1,%2,%3};"
        : "+f"(d[0]), "+f"(d[1]), "+f"(d[2]), "+f"(d[3])
        : "r"(a0), "r"(a1), "r"(a2), "r"(a3), "r"(b0), "r"(b1));
}
__device__ __forceinline__ void ldsm4(uint32_t r[4], uint32_t addr) {
    asm volatile("ldmatrix.sync.aligned.m8n8.x4.shared.b16 {%0,%1,%2,%3}, [%4];"
                 : "=r"(r[0]), "=r"(r[1]), "=r"(r[2]), "=r"(r[3]) : "r"(addr));
}

// blocked-swizzled store: 4 halfs at weight (n, k..k+3); K = inner dim of the matrix
__device__ __forceinline__ void store_blk(__half* base, int n, int k, int K, uint2 u) {
    int ntile = n >> 7, r = n & 127, kc = k >> 6, kk = k & 63;
    size_t byte = ((size_t)(ntile * (K >> 6) + kc) << 14) + ((size_t)r << 7)
                + (uint32_t)((kk * 2) ^ ((r & 7) << 4));
    *(uint2*)((char*)base + byte) = u;
}

// ---------------- GEMM core ----------------
// A: per-thread cp.async into padded rows. B: one cp.async.bulk/chunk into swizzled tile.
__device__ __forceinline__ void gemm_core(const __half* __restrict__ a_p,
                                          const char* __restrict__ bblk,
                                          int Ktot, char* sm, uint32_t sbu,
                                          float acc[2][8][4]) {
    const int t = threadIdx.x;
    const int lane = t & 31, wid = t >> 5;
    const int wm0 = (wid >> 1) * 32, wn0 = (wid & 1) * 64;
    const int nc = Ktot / KC;
    const int lrow = lane & 15, lhalf = lane >> 4;
    const int xorv = (lrow & 7) << 4;

    const uint32_t sA = sbu + SM_A + (t >> 1) * A_PITCH + (t & 1) * 64;
    const uint32_t lmA = sbu + SM_A + (wm0 + lrow) * A_PITCH + lhalf * 16;
    const uint32_t lmB = sbu + SM_B + (wn0 + lrow) * 128;
    const uint32_t mb0 = sbu + OFF_MB, mb1 = sbu + OFF_MB + 8;

    if (t == 0) { MBARRIER_INIT(mb0, 1); MBARRIER_INIT(mb1, 1); }
    __syncthreads();

    // prologue: chunk 0
#pragma unroll
    for (int q = 0; q < 4; q++) cpa16(sA + q * 16, a_p + q * 8);
    cpa_commit();
    if (t == 0) {
        mb_expect(mb0, B_BYTES);
        bulkcp(sbu + SM_B, bblk, B_BYTES, mb0);
    }

    int ph0 = 0, ph1 = 0;
    for (int c = 0; c < nc; c++) {
        const int s = c & 1;
        cpa_wait0();
        if (s == 0) { MBARRIER_WAIT_PARITY(mb0, ph0); ph0 ^= 1; }
        else        { MBARRIER_WAIT_PARITY(mb1, ph1); ph1 ^= 1; }
        __syncthreads();
        if (c + 1 < nc) {
            const uint32_t so = (1 - s) * STG;
            const __half* pa = a_p + (c + 1) * KC;
#pragma unroll
            for (int q = 0; q < 4; q++) cpa16(sA + so + q * 16, pa + q * 8);
            cpa_commit();
            if (t == 0) {
                uint32_t mbn = (s == 0) ? mb1 : mb0;
                mb_expect(mbn, B_BYTES);
                bulkcp(sbu + SM_B + so, bblk + (size_t)(c + 1) * B_BYTES, B_BYTES, mbn);
            }
        }
        const uint32_t stA = lmA + s * STG;
        const uint32_t stB = lmB + s * STG;
#pragma unroll
        for (int ks = 0; ks < KC / 16; ks++) {
            uint32_t ah[2][4];
#pragma unroll
            for (int mi = 0; mi < 2; mi++)
                ldsm4(ah[mi], stA + mi * 16 * A_PITCH + ks * 32);
            const uint32_t cb = (uint32_t)((lhalf * 16 + ks * 32) ^ xorv);
            uint32_t bb[4][4];
#pragma unroll
            for (int njp = 0; njp < 4; njp++)
                ldsm4(bb[njp], stB + njp * (16 * 128) + cb);
#pragma unroll
            for (int njp = 0; njp < 4; njp++)
#pragma unroll
                for (int sub = 0; sub < 2; sub++) {
                    int nj = njp * 2 + sub;
                    uint32_t b0 = bb[njp][sub];
                    uint32_t b1 = bb[njp][2 + sub];
#pragma unroll
                    for (int mi = 0; mi < 2; mi++)
                        mma16816(acc[mi][nj], ah[mi][0], ah[mi][1], ah[mi][2], ah[mi][3], b0, b1);
                }
        }
    }
}

// ---------------- transpose-convert into blocked-swizzled layout ----------------
__device__ __forceinline__ void cvt4(const float* __restrict__ s, __half* __restrict__ oh,
                                     int K, int N, int remap_half, int bx, int by, int t,
                                     float tile[32][33]) {
    int c0 = bx * 32, k0 = by * 32;
    int k = t >> 3, c4 = (t & 7) << 2;
    float4 v = *(const float4*)&s[(size_t)(k0 + k) * N + c0 + c4];
    tile[k][c4]     = v.x;
    tile[k][c4 + 1] = v.y;
    tile[k][c4 + 2] = v.z;
    tile[k][c4 + 3] = v.w;
    __syncthreads();
    int nl = t >> 3, kq = (t & 7) << 2;
    int cc = c0 + nl;
    int n = remap_half ? (2 * (cc % remap_half) + cc / remap_half) : cc;
    __half2 h0 = __floats2half2_rn(tile[kq][nl], tile[kq + 1][nl]);
    __half2 h1 = __floats2half2_rn(tile[kq + 2][nl], tile[kq + 3][nl]);
    uint2 u;
    u.x = *(uint32_t*)&h0;
    u.y = *(uint32_t*)&h1;
    store_blk(oh, n, k0 + kq, K, u);
}

// ---------------- merged prep: router + all weight conversions ----------------
__global__ __launch_bounds__(256) void k_prep(const float* __restrict__ x,
                                              const float* __restrict__ rw,
                                              float* __restrict__ out_logits,
                                              const float* __restrict__ gup,
                                              const float* __restrict__ dwn,
                                              const float* __restrict__ sgate,
                                              const float* __restrict__ sup,
                                              const float* __restrict__ sdown) {
    __shared__ float tile[32][33];
    int b = blockIdx.x, t = threadIdx.x;

    if (b < PREP_R) {
        // ---- router: 8 warps, 1 token each; fused x->fp16 ----
        int warp = t >> 5, lane = t & 31;
        int tok = b * 8 + warp;
        const float* xr = x + (size_t)tok * HDIM;
        __half* xo = g_x + (size_t)tok * HDIM;
        float acc[NE];
#pragma unroll
        for (int e = 0; e < NE; e++) acc[e] = 0.f;
        for (int i = lane; i < HDIM; i += 32) {
            float xv = xr[i];
            xo[i] = __float2half_rn(xv);
#pragma unroll
            for (int e = 0; e < NE; e++) acc[e] = fmaf(xv, rw[e * HDIM + i], acc[e]);
        }
#pragma unroll
        for (int e = 0; e < NE; e++) {
#pragma unroll
            for (int o = 16; o > 0; o >>= 1) acc[e] += __shfl_xor_sync(0xFFFFFFFFu, acc[e], o);
        }
        if (lane == 0) {
            if (out_logits) {
#pragma unroll
                for (int e = 0; e < NE; e++) out_logits[(size_t)tok * NE + e] = acc[e];
            }
            int e1 = 0; float v1 = acc[0];
#pragma unroll
            for (int e = 1; e < NE; e++) if (acc[e] > v1) { v1 = acc[e]; e1 = e; }
            int e2 = -1; float v2 = -1e30f;
#pragma unroll
            for (int e = 0; e < NE; e++) if (e != e1 && acc[e] > v2) { v2 = acc[e]; e2 = e; }
            g_tope[tok * 2 + 0] = e1; g_tops[tok * 2 + 0] = 1.f / (1.f + __expf(-v1));
            g_tope[tok * 2 + 1] = e2; g_tops[tok * 2 + 1] = 1.f / (1.f + __expf(-v2));
        }
    } else if (b < PREP_R + PREP_G) {
        int i = b - PREP_R;
        int bx = i & 127, by = (i >> 7) & 31, e = i >> 12;
        cvt4(gup + (size_t)e * HDIM * 2 * IDIM, g_wgu + (size_t)e * 2 * IDIM * HDIM,
             HDIM, 2 * IDIM, IDIM, bx, by, t, tile);
    } else if (b < PREP_R + PREP_G + PREP_D) {
        int i = b - PREP_R - PREP_G;
        int bx = i & 31, by = (i >> 5) & 63, e = i >> 11;
        cvt4(dwn + (size_t)e * IDIM * HDIM, g_wdn + (size_t)e * HDIM * IDIM,
             IDIM, HDIM, 0, bx, by, t, tile);
    } else {
        int i = b - PREP_R - PREP_G - PREP_D;
        size_t id = ((size_t)i * 256 + t) * 4;
        // shared gate/up: id over [I][H]
        int j = (int)(id / HDIM), k = (int)(id % HDIM);
        float4 gv = *(const float4*)(sgate + id);
        float4 uv = *(const float4*)(sup + id);
        uint2 ug, uu;
        {
            __half2 a = __floats2half2_rn(gv.x, gv.y), c = __floats2half2_rn(gv.z, gv.w);
            ug.x = *(uint32_t*)&a; ug.y = *(uint32_t*)&c;
            __half2 d = __floats2half2_rn(uv.x, uv.y), e2 = __floats2half2_rn(uv.z, uv.w);
            uu.x = *(uint32_t*)&d; uu.y = *(uint32_t*)&e2;
        }
        store_blk(g_wsg, 2 * j, k, HDIM, ug);
        store_blk(g_wsg, 2 * j + 1, k, HDIM, uu);
        // shared down: id over [H][I]
        int n = (int)(id / IDIM), kk = (int)(id % IDIM);
        float4 v = *(const float4*)(sdown + id);
        uint2 ud;
        {
            __half2 a = __floats2half2_rn(v.x, v.y), c = __floats2half2_rn(v.z, v.w);
            ud.x = *(uint32_t*)&a; ud.y = *(uint32_t*)&c;
        }
        store_blk(g_wsd, n, kk, IDIM, ud);
    }
}

// ---------------- single-CTA scatter ----------------
__global__ __launch_bounds__(1024) void k_scatter_all() {
    __shared__ int cnt[NE], off[NE], cur[NE];
    int tid = threadIdx.x;
    if (tid < NE) cnt[tid] = 0;
    __syncthreads();
    for (int p = tid; p < NPAIR; p += 1024)
        atomicAdd(&cnt[g_tope[p]], 1);
    __syncthreads();
    if (tid == 0) {
        int s = 0;
        for (int e = 0; e < NE; e++) { off[e] = s; s += cnt[e]; cur[e] = 0; }
    }
    __syncthreads();
    for (int p = tid; p < NPAIR; p += 1024) {
        int e = g_tope[p];
        int pos = atomicAdd(&cur[e], 1);
        int r = off[e] + pos;
        g_row_tok[r]  = p >> 1;
        g_row_sc[r]   = g_tops[p];
        g_row_slot[r] = p & 1;
    }
    if (tid < NE) { g_cnt[tid] = cnt[tid]; g_off[tid] = off[tid]; }
}

// ---------------- GEMM layer 1: routed gate_up (y<256) + shared gate_up (y>=256) ----------------
__global__ __launch_bounds__(256, 2) void tc_l1() {
    extern __shared__ char sm[];
    uint32_t sbu = smem_u32(sm);
    int t = threadIdx.x;
    int lane = t & 31, wid = t >> 5, g = lane >> 2, tg = lane & 3;
    int wm0 = (wid >> 1) * 32, wn0 = (wid & 1) * 64;
    int n0 = blockIdx.x * 128;
    int rb = t >> 1, half = t & 1;

    float acc[2][8][4];
#pragma unroll
    for (int a = 0; a < 2; a++)
#pragma unroll
        for (int b = 0; b < 8; b++)
#pragma unroll
            for (int q = 0; q < 4; q++) acc[a][b][q] = 0.f;

    int jcb = wn0 / 2 + tg;
    __half* ep = (__half*)sm;

    if (blockIdx.y < 256) {
        // ---- routed gate_up ----
        int e = blockIdx.y >> 5, rt = blockIdx.y & 31;
        int cnt = g_cnt[e];
        int row0 = rt * 128;
        if (row0 >= cnt) return;
        int base = g_off[e];
        int rr = base + min(row0 + rb, cnt - 1);
        const __half* ap = g_x + (size_t)g_row_tok[rr] * HDIM + half * 32;
        const char* bblk = (const char*)g_wgu + (size_t)e * 2 * IDIM * HDIM * 2
                         + (size_t)(n0 >> 7) * (HDIM >> 6) * B_BYTES;

        gemm_core(ap, bblk, HDIM, sm, sbu, acc);
        __syncthreads();

#pragma unroll
        for (int mi = 0; mi < 2; mi++)
#pragma unroll
            for (int dq = 0; dq < 2; dq++) {
                int rl = wm0 + mi * 16 + g + dq * 8;
                if (row0 + rl < cnt) {
                    float sc = g_row_sc[base + row0 + rl];
#pragma unroll
                    for (int nj = 0; nj < 8; nj++) {
                        float v = silu_mul(sc * acc[mi][nj][dq * 2], sc * acc[mi][nj][dq * 2 + 1]);
                        ep[rl * EP_PITCH + jcb + nj * 4] = __float2half_rn(v);
                    }
                }
            }
        __syncthreads();
        {
            int r = t >> 1, cseg = (t & 1) * 32;
            if (row0 + r < cnt) {
                int grow = base + row0 + r;
                const uint4* src = (const uint4*)(ep + r * EP_PITCH + cseg);
                uint4* dst = (uint4*)(g_act + (size_t)grow * IDIM + n0 / 2 + cseg);
#pragma unroll
                for (int q = 0; q < 4; q++) dst[q] = src[q];
            }
        }
    } else {
        // ---- shared gate_up ----
        int row0 = (blockIdx.y - 256) * 128;
        const __half* ap = g_x + (size_t)(row0 + rb) * HDIM + half * 32;
        const char* bblk = (const char*)g_wsg + (size_t)(n0 >> 7) * (HDIM >> 6) * B_BYTES;

        gemm_core(ap, bblk, HDIM, sm, sbu, acc);
        __syncthreads();

#pragma unroll
        for (int mi = 0; mi < 2; mi++)
#pragma unroll
            for (int dq = 0; dq < 2; dq++) {
                int rl = wm0 + mi * 16 + g + dq * 8;
#pragma unroll
                for (int nj = 0; nj < 8; nj++) {
                    float v = silu_mul(acc[mi][nj][dq * 2], acc[mi][nj][dq * 2 + 1]);
                    ep[rl * EP_PITCH + jcb + nj * 4] = __float2half_rn(v);
                }
            }
        __syncthreads();
        {
            int r = t >> 1, cseg = (t & 1) * 32;
            const uint4* src = (const uint4*)(ep + r * EP_PITCH + cseg);
            uint4* dst = (uint4*)(g_acts + (size_t)(row0 + r) * IDIM + n0 / 2 + cseg);
#pragma unroll
            for (int q = 0; q < 4; q++) dst[q] = src[q];
        }
    }
}

// ---------------- GEMM layer 2: routed down ----------------
__global__ __launch_bounds__(256, 2) void tc_dn_routed() {
    int e = blockIdx.y >> 5, rt = blockIdx.y & 31;
    int cnt = g_cnt[e];
    int row0 = rt * 128;
    if (row0 >= cnt) return;
    int base = g_off[e];

    extern __shared__ char sm[];
    uint32_t sbu = smem_u32(sm);
    int t = threadIdx.x, rb = t >> 1, half = t & 1;
    const __half* ap = g_act + (size_t)(base + min(row0 + rb, cnt - 1)) * IDIM + half * 32;
    int n0 = blockIdx.x * 128;
    const char* bblk = (const char*)g_wdn + (size_t)e * HDIM * IDIM * 2
                     + (size_t)(n0 >> 7) * (IDIM >> 6) * B_BYTES;

    float acc[2][8][4];
#pragma unroll
    for (int a = 0; a < 2; a++)
#pragma unroll
        for (int b = 0; b < 8; b++)
#pragma unroll
            for (int q = 0; q < 4; q++) acc[a][b][q] = 0.f;

    gemm_core(ap, bblk, IDIM, sm, sbu, acc);

    int lane = t & 31, wid = t >> 5, g = lane >> 2, tg = lane & 3;
    int wm0 = (wid >> 1) * 32, wn0 = (wid & 1) * 64;
    int colb = n0 + wn0 + tg * 2;
#pragma unroll
    for (int mi = 0; mi < 2; mi++)
#pragma unroll
        for (int dq = 0; dq < 2; dq++) {
            int rl = wm0 + mi * 16 + g + dq * 8;
            if (row0 + rl < cnt) {
                int grow = base + row0 + rl;
                int tok = g_row_tok[grow], slot = g_row_slot[grow];
                float* dst = g_partial[slot] + (size_t)tok * HDIM;
#pragma unroll
                for (int nj = 0; nj < 8; nj++) {
                    float2 v = {acc[mi][nj][dq * 2], acc[mi][nj][dq * 2 + 1]};
                    *(float2*)&dst[colb + nj * 8] = v;
                }
            }
        }
}

// ---------------- GEMM layer 3: shared down + final add ----------------
__global__ __launch_bounds__(256, 2) void tc_dn_shared(float* __restrict__ out) {
    int row0 = blockIdx.y * 128;
    int n0 = blockIdx.x * 128;

    extern __shared__ char sm[];
    uint32_t sbu = smem_u32(sm);
    int t = threadIdx.x, rb = t >> 1, half = t & 1;
    const __half* ap = g_acts + (size_t)(row0 + rb) * IDIM + half * 32;
    const char* bblk = (const char*)g_wsd + (size_t)(n0 >> 7) * (IDIM >> 6) * B_BYTES;

    float acc[2][8][4];
#pragma unroll
    for (int a = 0; a < 2; a++)
#pragma unroll
        for (int b = 0; b < 8; b++)
#pragma unroll
            for (int q = 0; q < 4; q++) acc[a][b][q] = 0.f;

    gemm_core(ap, bblk, IDIM, sm, sbu, acc);

    int lane = t & 31, wid = t >> 5, g = lane >> 2, tg = lane & 3;
    int wm0 = (wid >> 1) * 32, wn0 = (wid & 1) * 64;
    int colb = n0 + wn0 + tg * 2;
#pragma unroll
    for (int mi = 0; mi < 2; mi++)
#pragma unroll
        for (int dq = 0; dq < 2; dq++) {
            int row = row0 + wm0 + mi * 16 + g + dq * 8;
            size_t rbase = (size_t)row * HDIM;
#pragma unroll
            for (int nj = 0; nj < 8; nj++) {
                size_t idx = rbase + colb + nj * 8;
                float2 p0 = *(const float2*)&g_partial[0][idx];
                float2 p1 = *(const float2*)&g_partial[1][idx];
                float2 v;
                v.x = acc[mi][nj][dq * 2] + p0.x + p1.x;
                v.y = acc[mi][nj][dq * 2 + 1] + p0.y + p1.y;
                *(float2*)&out[idx] = v;
            }
        }
}

// ---------------- launch ----------------
extern "C" void kernel_launch(void* const* d_in, const int* in_sizes, int n_in,
                              void* d_out, int out_size) {
    const float* x     = (const float*)d_in[0];   // [T, H]
    const float* rw    = (const float*)d_in[1];   // [E, H]
    const float* gup   = (const float*)d_in[2];   // [E, H, 2I]
    const float* dwn   = (const float*)d_in[3];   // [E, I, H]
    const float* sgate = (const float*)d_in[4];   // [I, H]
    const float* sup   = (const float*)d_in[5];   // [I, H]
    const float* sdown = (const float*)d_in[6];   // [H, I]
    float* out = (float*)d_out;

    float* out_logits = nullptr;
    if (out_size >= TTOK * HDIM + TTOK * NE) out_logits = out + (size_t)TTOK * HDIM;

    cudaFuncSetAttribute(tc_l1,        cudaFuncAttributeMaxDynamicSharedMemorySize, SMEM_GEMM);
    cudaFuncSetAttribute(tc_dn_routed, cudaFuncAttributeMaxDynamicSharedMemorySize, SMEM_GEMM);
    cudaFuncSetAttribute(tc_dn_shared, cudaFuncAttributeMaxDynamicSharedMemorySize, SMEM_GEMM);

    k_prep<<<PREP_TOTAL, 256>>>(x, rw, out_logits, gup, dwn, sgate, sup, sdown);
    k_scatter_all<<<1, 1024>>>();

    tc_l1<<<dim3(2 * IDIM / 128, 256 + TTOK / 128), 256, SMEM_GEMM>>>();
    tc_dn_routed<<<dim3(HDIM / 128, NE * 32), 256, SMEM_GEMM>>>();
    tc_dn_shared<<<dim3(HDIM / 128, TTOK / 128), 256, SMEM_GEMM>>>(out);
}